// round 8
// baseline (speedup 1.0000x reference)
#include <cuda_runtime.h>
#include <cuda_bf16.h>
#include <cstdint>

#define Dv 512
#define Rv 64
#define TM 128
#define NTHREADS 256

// ---------------------------------------------------------------------------
// Device scratch: pre-packed bf16 hi/lo operand tiles, 128B rows, SW128
// ---------------------------------------------------------------------------
__device__ __align__(16) __nv_bfloat16 g_Abh[8 * 64 * 64];   // chunk c: [r][kk]
__device__ __align__(16) __nv_bfloat16 g_Abl[8 * 64 * 64];
__device__ __align__(16) __nv_bfloat16 g_Vbh[4 * 128 * 64];  // n-chunk j: [n][r]
__device__ __align__(16) __nv_bfloat16 g_Vbl[4 * 128 * 64];

// ---------------------------------------------------------------------------
// Helpers
// ---------------------------------------------------------------------------
#define SWZ(o) ((o) ^ (((o) >> 3) & 0x70))

__device__ __forceinline__ uint32_t smem_to_u32(const void* p) {
    uint32_t a;
    asm("{ .reg .u64 t; cvta.to.shared.u64 t, %1; cvt.u32.u64 %0, t; }" : "=r"(a) : "l"(p));
    return a;
}
__device__ __forceinline__ void ldsm4(uint32_t* r, uint32_t addr) {
    asm volatile("ldmatrix.sync.aligned.m8n8.x4.shared.b16 {%0,%1,%2,%3}, [%4];"
                 : "=r"(r[0]), "=r"(r[1]), "=r"(r[2]), "=r"(r[3]) : "r"(addr));
}
__device__ __forceinline__ void mma16816(float* c, const uint32_t* a,
                                         uint32_t b0, uint32_t b1) {
    asm volatile("mma.sync.aligned.m16n8k16.row.col.f32.bf16.bf16.f32 "
                 "{%0,%1,%2,%3}, {%4,%5,%6,%7}, {%8,%9}, {%0,%1,%2,%3};"
                 : "+f"(c[0]), "+f"(c[1]), "+f"(c[2]), "+f"(c[3])
                 : "r"(a[0]), "r"(a[1]), "r"(a[2]), "r"(a[3]), "r"(b0), "r"(b1));
}
__device__ __forceinline__ void sts128(uint32_t a, uint32_t x, uint32_t y,
                                       uint32_t z, uint32_t w) {
    asm volatile("st.shared.v4.b32 [%0], {%1,%2,%3,%4};"
                 :: "r"(a), "r"(x), "r"(y), "r"(z), "r"(w) : "memory");
}
__device__ __forceinline__ float4 lds128(uint32_t a) {
    float4 v;
    asm volatile("ld.shared.v4.f32 {%0,%1,%2,%3}, [%4];"
                 : "=f"(v.x), "=f"(v.y), "=f"(v.z), "=f"(v.w) : "r"(a));
    return v;
}
__device__ __forceinline__ void cpasync16(uint32_t dst, const void* src) {
    asm volatile("cp.async.cg.shared.global [%0], [%1], 16;"
                 :: "r"(dst), "l"(src) : "memory");
}
#define CP_COMMIT() asm volatile("cp.async.commit_group;" ::: "memory")
#define CP_WAIT(N)  asm volatile("cp.async.wait_group %0;" :: "n"(N) : "memory")

__device__ __forceinline__ uint32_t cvt2(float f0, float f1) {
    uint32_t r;
    asm("cvt.rn.bf16x2.f32 %0, %1, %2;" : "=r"(r) : "f"(f1), "f"(f0));
    return r;
}
__device__ __forceinline__ float bl(uint32_t h) { return __uint_as_float(h << 16); }
__device__ __forceinline__ float bh(uint32_t h) { return __uint_as_float(h & 0xFFFF0000u); }

// ---------------------------------------------------------------------------
// Single precompute kernel: 12 blocks x 512 threads.
//  All blocks stream P's 8 slabs (64x64) through smem.
//  Blocks 0-7:  full Gram (regs) -> rv -> GT -> back-sub W -> W2 -> pack A chunk
//  Blocks 8-11: diag only -> rv -> pack V n-chunk
// smem float offsets:
// ---------------------------------------------------------------------------
#define PR_RV  0            // 64
#define PR_GT  64           // 64*65  (Gram^T scaled; later W2)
#define PR_SW  4224         // 64*64  (back-sub solutions)
#define PR_SP  8320         // 64*68  (slab buffer, stride 68 for float4)
#define PR_PV  64           // 128*65 (V rows; overlaps GT/SW — V blocks only)
#define PR_SPV 8384         // 64*68  (V-path slab buffer)
#define PR_FLOATS 12736

__global__ __launch_bounds__(512) void k_prep(const float* __restrict__ P) {
    extern __shared__ float sm[];
    int bid = blockIdx.x, tid = threadIdx.x, w = tid >> 5, lane = tid & 31;

    if (bid < 8) {
        int c = bid;
        int j = tid >> 3, k0 = (tid & 7) << 3;
        float g8[8] = {};
        for (int b = 0; b < 8; b++) {
            __syncthreads();
            for (int idx = tid; idx < 4096; idx += 512)
                sm[PR_SP + (idx >> 6) * 68 + (idx & 63)] = P[b * 4096 + idx];
            __syncthreads();
            #pragma unroll 2
            for (int d = 0; d < 64; d++) {
                float vj = sm[PR_SP + d * 68 + j];
                float4 a  = *(const float4*)&sm[PR_SP + d * 68 + k0];
                float4 c4 = *(const float4*)&sm[PR_SP + d * 68 + k0 + 4];
                g8[0] += vj * a.x;  g8[1] += vj * a.y;
                g8[2] += vj * a.z;  g8[3] += vj * a.w;
                g8[4] += vj * c4.x; g8[5] += vj * c4.y;
                g8[6] += vj * c4.z; g8[7] += vj * c4.w;
            }
        }
        // diag -> rv
        if ((j >> 3) == (tid & 7)) sm[PR_RV + j] = g8[j & 7];
        __syncthreads();
        if (tid < 64) sm[PR_RV + tid] = rsqrtf(sm[PR_RV + tid]);
        __syncthreads();
        // GT[i][jj] = 2*G[jj][i]*rv[i]*rv[jj]; this thread has G[j][k0+e]
        float rvj = sm[PR_RV + j];
        #pragma unroll
        for (int e = 0; e < 8; e++)
            sm[PR_GT + (k0 + e) * 65 + j] = 2.f * g8[e] * sm[PR_RV + k0 + e] * rvj;
        __syncthreads();
        // back-substitution: W = M^-1 (upper tri), 16 warps x 4 columns
        for (int k = w; k < 64; k += 16) {
            for (int i = lane; i < 64; i += 32)
                sm[PR_SW + k * 64 + i] = (i == k) ? 1.f : 0.f;
            __syncwarp();
            for (int i = k - 1; i >= 0; i--) {
                float s = 0.f;
                for (int jj = i + 1 + lane; jj <= k; jj += 32)
                    s += sm[PR_GT + i * 65 + jj] * sm[PR_SW + k * 64 + jj];
                #pragma unroll
                for (int o = 16; o; o >>= 1) s += __shfl_xor_sync(0xFFFFFFFFu, s, o);
                if (lane == 0) sm[PR_SW + k * 64 + i] = -s;
                __syncwarp();
            }
        }
        __syncthreads();
        // W2[jj][r] = 2 rv[jj] W[jj][r]  (into GT region)
        for (int idx = tid; idx < 4096; idx += 512) {
            int jj = idx >> 6, r = idx & 63;
            float v = (jj < r) ? 2.f * sm[PR_RV + jj] * sm[PR_SW + r * 64 + jj]
                               : (jj == r ? 2.f * sm[PR_RV + jj] : 0.f);
            sm[PR_GT + jj * 65 + r] = v;
        }
        __syncthreads();
        // reload slab c (was overwritten during streaming)
        for (int idx = tid; idx < 4096; idx += 512)
            sm[PR_SP + (idx >> 6) * 68 + (idx & 63)] = P[c * 4096 + idx];
        __syncthreads();
        // A'[r][kk] = sum_j P[kk][j] * W2[j][r]; pack bf16 hi/lo swizzled
        int rr = tid & 63, kb = (tid >> 6) << 3;
        float acc[8] = {};
        #pragma unroll 4
        for (int jj = 0; jj < 64; jj++) {
            float wv = sm[PR_GT + jj * 65 + rr];
            #pragma unroll
            for (int e = 0; e < 8; e++)
                acc[e] += sm[PR_SP + (kb + e) * 68 + jj] * wv;
        }
        #pragma unroll
        for (int e = 0; e < 8; e++) {
            float v = acc[e];
            __nv_bfloat16 h = __float2bfloat16_rn(v);
            float lo = v - __bfloat162float(h);
            uint32_t off = c * 8192 + SWZ((uint32_t)(rr * 128 + (kb + e) * 2));
            *(__nv_bfloat16*)((char*)g_Abh + off) = h;
            *(__nv_bfloat16*)((char*)g_Abl + off) = __float2bfloat16_rn(lo);
        }
    } else {
        int jn = bid - 8;
        float dacc = 0.f;
        for (int b = 0; b < 8; b++) {
            __syncthreads();
            for (int idx = tid; idx < 4096; idx += 512)
                sm[PR_SPV + (idx >> 6) * 68 + (idx & 63)] = P[b * 4096 + idx];
            __syncthreads();
            if (tid < 64) {
                #pragma unroll 8
                for (int d = 0; d < 64; d++) {
                    float v = sm[PR_SPV + d * 68 + tid];
                    dacc += v * v;
                }
            }
        }
        // load this n-chunk's 128 P rows
        for (int idx = tid; idx < 8192; idx += 512)
            sm[PR_PV + (idx >> 6) * 65 + (idx & 63)] =
                P[(jn * 128 + (idx >> 6)) * 64 + (idx & 63)];
        if (tid < 64) sm[PR_RV + tid] = rsqrtf(dacc);
        __syncthreads();
        for (int idx = tid; idx < 8192; idx += 512) {
            int n = idx >> 6, r = idx & 63;
            float v = sm[PR_PV + n * 65 + r] * sm[PR_RV + r];
            __nv_bfloat16 h = __float2bfloat16_rn(v);
            float lo = v - __bfloat162float(h);
            uint32_t off = jn * 16384 + SWZ((uint32_t)(n * 128 + r * 2));
            *(__nv_bfloat16*)((char*)g_Vbh + off) = h;
            *(__nv_bfloat16*)((char*)g_Vbl + off) = __float2bfloat16_rn(lo);
        }
    }
}

// ---------------------------------------------------------------------------
// Main kernel. smem (96KB, 2 CTA/SM):
//   [0,     32768)  stage: raw fp32 X chunk (cp.async) / V buffers 0,3
//   [32768, 65536)  Xh/Xl bf16                          / V buffer 2
//   [65536, 98304)  A ping/pong 16K each                / V buffer 1
// ---------------------------------------------------------------------------
#define OFF_STAGE 0
#define OFF_XH    32768
#define OFF_XL    49152
#define OFF_A0    65536
#define OFF_A1    81920
#define SMEM_BYTES 98304

__global__ __launch_bounds__(NTHREADS, 2) void k_gemm(const float* __restrict__ x,
                                                      float* __restrict__ out,
                                                      const float* __restrict__ sldj,
                                                      float* __restrict__ outSldj) {
    extern __shared__ char smem[];
    uint32_t sb = smem_to_u32(smem);
    const uint32_t sStage = sb + OFF_STAGE;
    const uint32_t sXh = sb + OFF_XH, sXl = sb + OFF_XL;

    int tid = threadIdx.x, wid = tid >> 5, lane = tid & 31;
    int m0 = blockIdx.x * TM;
    int mw = wid << 4;

    uint32_t lrow = lane & 15;
    uint32_t lcolb = (lane >> 4) << 4;
    uint32_t xw = (lrow & 7) << 4;
    uint32_t arowb = (mw + lrow) * 128;

    auto issueX = [&](int c) {
        for (int idx = tid; idx < 2048; idx += NTHREADS) {
            int r = idx >> 4, i = idx & 15;
            uint32_t dst = sStage + r * 256 + (((uint32_t)(i * 16)) ^ ((r & 7) << 5));
            const char* src = (const char*)(x + (size_t)(m0 + r) * Dv + c * 64 + i * 4);
            cpasync16(dst, src);
        }
    };
    auto issueA = [&](int c, uint32_t buf) {
        const char* srch = (const char*)g_Abh + c * 8192;
        const char* srcl = (const char*)g_Abl + c * 8192;
        for (int idx = tid; idx < 512; idx += NTHREADS) {
            cpasync16(buf + idx * 16, srch + idx * 16);
            cpasync16(buf + 8192 + idx * 16, srcl + idx * 16);
        }
    };
    auto issueV = [&](int j, uint32_t bufh, uint32_t bufl) {
        const char* srch = (const char*)g_Vbh + j * 16384;
        const char* srcl = (const char*)g_Vbl + j * 16384;
        for (int idx = tid; idx < 1024; idx += NTHREADS) {
            cpasync16(bufh + idx * 16, srch + idx * 16);
            cpasync16(bufl + idx * 16, srcl + idx * 16);
        }
    };

    float acc[8][4];
    #pragma unroll
    for (int i = 0; i < 8; i++)
        acc[i][0] = acc[i][1] = acc[i][2] = acc[i][3] = 0.f;

    issueX(0); issueA(0, sb + OFF_A0); CP_COMMIT();

    // ================= Phase 1: Y = X A  (8 k-chunks of 64) =================
    for (int c = 0; c < 8; c++) {
        CP_WAIT(0);
        __syncthreads();
        // convert stage -> Xh/Xl (bf16 hi/lo, SW128)
        #pragma unroll
        for (int p = 0; p < 4; p++) {
            int it = tid + p * NTHREADS;
            int row = it >> 3, g = it & 7;
            uint32_t sa = sStage + row * 256 + (((uint32_t)(g * 32)) ^ ((row & 7) << 5));
            float4 v0 = lds128(sa);
            float4 v1 = lds128(sa + 16);
            float f[8] = {v0.x, v0.y, v0.z, v0.w, v1.x, v1.y, v1.z, v1.w};
            uint32_t H[4], L[4];
            #pragma unroll
            for (int q = 0; q < 4; q++) {
                uint32_t h = cvt2(f[2 * q], f[2 * q + 1]);
                H[q] = h;
                L[q] = cvt2(f[2 * q] - bl(h), f[2 * q + 1] - bh(h));
            }
            uint32_t ad = row * 128 + (((uint32_t)(g * 16)) ^ ((row & 7) << 4));
            sts128(sXh + ad, H[0], H[1], H[2], H[3]);
            sts128(sXl + ad, L[0], L[1], L[2], L[3]);
        }
        __syncthreads();
        if (c < 7) {
            issueX(c + 1);
            issueA(c + 1, sb + ((c + 1) & 1 ? OFF_A1 : OFF_A0));
            CP_COMMIT();
        } else {
            issueV(0, sStage, sStage + 16384);   // stage free after conversion
            CP_COMMIT();
        }
        uint32_t bufAh = sb + ((c & 1) ? OFF_A1 : OFF_A0);
        uint32_t bufAl = bufAh + 8192;
        #pragma unroll
        for (int ks = 0; ks < 4; ks++) {
            uint32_t ic = (lcolb + ks * 32) ^ xw;
            uint32_t ah[4], al[4];
            ldsm4(ah, sXh + arowb + ic);
            ldsm4(al, sXl + arowb + ic);
            #pragma unroll
            for (int p = 0; p < 4; p++) {
                uint32_t ro = (lrow + p * 16) * 128;
                uint32_t bhr[4], blr[4];
                ldsm4(bhr, bufAh + ro + ic);
                ldsm4(blr, bufAl + ro + ic);
                mma16816(acc[2 * p],     ah, bhr[0], bhr[2]);
                mma16816(acc[2 * p],     ah, blr[0], blr[2]);
                mma16816(acc[2 * p],     al, bhr[0], bhr[2]);
                mma16816(acc[2 * p + 1], ah, bhr[1], bhr[3]);
                mma16816(acc[2 * p + 1], ah, blr[1], blr[3]);
                mma16816(acc[2 * p + 1], al, bhr[1], bhr[3]);
            }
        }
    }
    __syncthreads();                       // MMA(7) done: A + X regions free
    issueV(1, sb + OFF_A0, sb + OFF_A1); CP_COMMIT();
    issueV(2, sXh, sXl);                 CP_COMMIT();

    // ======= Y: register repack acc (C-frag) -> phase-2 A-frags (hi/lo) =====
    uint32_t yh[4][4], yl[4][4];
    #pragma unroll
    for (int kb = 0; kb < 4; kb++) {
        uint32_t h;
        h = cvt2(acc[2*kb][0],   acc[2*kb][1]);   yh[kb][0] = h;
        yl[kb][0] = cvt2(acc[2*kb][0] - bl(h),    acc[2*kb][1] - bh(h));
        h = cvt2(acc[2*kb][2],   acc[2*kb][3]);   yh[kb][1] = h;
        yl[kb][1] = cvt2(acc[2*kb][2] - bl(h),    acc[2*kb][3] - bh(h));
        h = cvt2(acc[2*kb+1][0], acc[2*kb+1][1]); yh[kb][2] = h;
        yl[kb][2] = cvt2(acc[2*kb+1][0] - bl(h),  acc[2*kb+1][1] - bh(h));
        h = cvt2(acc[2*kb+1][2], acc[2*kb+1][3]); yh[kb][3] = h;
        yl[kb][3] = cvt2(acc[2*kb+1][2] - bl(h),  acc[2*kb+1][3] - bh(h));
    }

    // ================= Phase 2: Z = Y V^T, out = X - Z  (4 n-chunks) ========
    const uint32_t vhOff[4] = {OFF_STAGE, OFF_A0, OFF_XH, OFF_STAGE};
    const uint32_t vlOff[4] = {OFF_STAGE + 16384, OFF_A1, OFF_XL, OFF_STAGE + 16384};
    #pragma unroll
    for (int j = 0; j < 4; j++) {
        if (j <= 1) { CP_WAIT(2); } else if (j == 2) { CP_WAIT(1); } else { CP_WAIT(0); }
        __syncthreads();
        uint32_t bufVh = sb + vhOff[j], bufVl = sb + vlOff[j];

        float z[16][4];
        #pragma unroll
        for (int i = 0; i < 16; i++)
            z[i][0] = z[i][1] = z[i][2] = z[i][3] = 0.f;

        #pragma unroll
        for (int ks = 0; ks < 4; ks++) {
            uint32_t ic = (lcolb + ks * 32) ^ xw;
            #pragma unroll
            for (int p = 0; p < 8; p++) {
                uint32_t ro = (lrow + p * 16) * 128;
                uint32_t bhr[4], blr[4];
                ldsm4(bhr, bufVh + ro + ic);
                ldsm4(blr, bufVl + ro + ic);
                mma16816(z[2 * p],     yh[ks], bhr[0], bhr[2]);
                mma16816(z[2 * p],     yh[ks], blr[0], blr[2]);
                mma16816(z[2 * p],     yl[ks], bhr[0], bhr[2]);
                mma16816(z[2 * p + 1], yh[ks], bhr[1], bhr[3]);
                mma16816(z[2 * p + 1], yh[ks], blr[1], blr[3]);
                mma16816(z[2 * p + 1], yl[ks], bhr[1], bhr[3]);
            }
        }
        if (j == 0) {   // all warps done reading V0 -> stage free for V3
            __syncthreads();
            issueV(3, sStage, sStage + 16384);
            CP_COMMIT();
        }

        // epilogue: out = x - z (fragment-mapped float2; x re-read hits L2)
        int r0 = m0 + mw + (lane >> 2);
        const float* x0p = x + (size_t)r0 * Dv;
        const float* x1p = x0p + 8 * Dv;
        float* o0 = out + (size_t)r0 * Dv;
        float* o1 = o0 + 8 * Dv;
        int cbase = (j << 7) + ((lane & 3) << 1);
        #pragma unroll
        for (int nt = 0; nt < 16; nt++) {
            int cc = cbase + nt * 8;
            float2 a0 = *(const float2*)(x0p + cc);
            float2 a1 = *(const float2*)(x1p + cc);
            float2 w0 = make_float2(a0.x - z[nt][0], a0.y - z[nt][1]);
            float2 w1 = make_float2(a1.x - z[nt][2], a1.y - z[nt][3]);
            *(float2*)(o0 + cc) = w0;
            *(float2*)(o1 + cc) = w1;
        }
    }

    if (outSldj != nullptr && tid < TM) {
        outSldj[m0 + tid] = sldj[m0 + tid];
    }
}

extern "C" void kernel_launch(void* const* d_in, const int* in_sizes, int n_in,
                              void* d_out, int out_size) {
    const float* x    = (const float*)d_in[0];   // (B, D)
    const float* sldj = (const float*)d_in[1];   // (B,)
    const float* P    = (const float*)d_in[2];   // (D, R)
    int BD = in_sizes[0];
    int Bn = in_sizes[1];
    (void)n_in;
    float* out = (float*)d_out;
    float* osl = (out_size >= BD + Bn) ? (out + BD) : nullptr;

    cudaFuncSetAttribute(k_prep, cudaFuncAttributeMaxDynamicSharedMemorySize,
                         PR_FLOATS * 4);
    k_prep<<<12, 512, PR_FLOATS * 4>>>(P);

    cudaFuncSetAttribute(k_gemm, cudaFuncAttributeMaxDynamicSharedMemorySize, SMEM_BYTES);
    k_gemm<<<Bn / TM, NTHREADS, SMEM_BYTES>>>(x, out, sldj, osl);
}

// round 9
// speedup vs baseline: 1.2015x; 1.2015x over previous
#include <cuda_runtime.h>
#include <cuda_bf16.h>
#include <cstdint>

#define Dv 512
#define Rv 64
#define TM 128
#define NTHREADS 256

// ---------------------------------------------------------------------------
// Device scratch
// ---------------------------------------------------------------------------
__device__ float g_G[64 * 64];    // Gram matrix G = P^T P
// Pre-packed bf16 hi/lo operand tiles, 128B rows, SW128-swizzled
__device__ __align__(16) __nv_bfloat16 g_Abh[8 * 64 * 64];   // chunk c: [r][kk]
__device__ __align__(16) __nv_bfloat16 g_Abl[8 * 64 * 64];
__device__ __align__(16) __nv_bfloat16 g_Vbh[4 * 128 * 64];  // n-chunk j: [n][r]
__device__ __align__(16) __nv_bfloat16 g_Vbl[4 * 128 * 64];

// ---------------------------------------------------------------------------
// Helpers
// ---------------------------------------------------------------------------
#define SWZ(o) ((o) ^ (((o) >> 3) & 0x70))

__device__ __forceinline__ uint32_t smem_to_u32(const void* p) {
    uint32_t a;
    asm("{ .reg .u64 t; cvta.to.shared.u64 t, %1; cvt.u32.u64 %0, t; }" : "=r"(a) : "l"(p));
    return a;
}
__device__ __forceinline__ void ldsm4(uint32_t* r, uint32_t addr) {
    asm volatile("ldmatrix.sync.aligned.m8n8.x4.shared.b16 {%0,%1,%2,%3}, [%4];"
                 : "=r"(r[0]), "=r"(r[1]), "=r"(r[2]), "=r"(r[3]) : "r"(addr));
}
__device__ __forceinline__ void mma16816(float* c, const uint32_t* a,
                                         uint32_t b0, uint32_t b1) {
    asm volatile("mma.sync.aligned.m16n8k16.row.col.f32.bf16.bf16.f32 "
                 "{%0,%1,%2,%3}, {%4,%5,%6,%7}, {%8,%9}, {%0,%1,%2,%3};"
                 : "+f"(c[0]), "+f"(c[1]), "+f"(c[2]), "+f"(c[3])
                 : "r"(a[0]), "r"(a[1]), "r"(a[2]), "r"(a[3]), "r"(b0), "r"(b1));
}
__device__ __forceinline__ void cpasync16(uint32_t dst, const void* src) {
    asm volatile("cp.async.cg.shared.global [%0], [%1], 16;"
                 :: "r"(dst), "l"(src) : "memory");
}
#define CP_COMMIT() asm volatile("cp.async.commit_group;" ::: "memory")
#define CP_WAIT(N)  asm volatile("cp.async.wait_group %0;" :: "n"(N) : "memory")

__device__ __forceinline__ uint32_t cvt2(float f0, float f1) {
    uint32_t r;
    asm("cvt.rn.bf16x2.f32 %0, %1, %2;" : "=r"(r) : "f"(f1), "f"(f0));
    return r;
}
__device__ __forceinline__ float bl(uint32_t h) { return __uint_as_float(h << 16); }
__device__ __forceinline__ float bh(uint32_t h) { return __uint_as_float(h & 0xFFFF0000u); }

// ---------------------------------------------------------------------------
// Precompute 1: full Gram G = P^T P, 16 blocks x 256 thr (4 G-rows per block)
// ---------------------------------------------------------------------------
__global__ __launch_bounds__(256) void k_gram(const float* __restrict__ P) {
    __shared__ float sP[64 * 68];
    int b = blockIdx.x, tid = threadIdx.x;
    int j = b * 4 + (tid >> 6);          // G row
    int k = tid & 63;                    // G col
    float acc = 0.f;
    for (int s = 0; s < 8; s++) {
        __syncthreads();
        for (int idx = tid; idx < 4096; idx += 256)
            sP[(idx >> 6) * 68 + (idx & 63)] = P[s * 4096 + idx];
        __syncthreads();
        #pragma unroll 8
        for (int d = 0; d < 64; d++)
            acc += sP[d * 68 + j] * sP[d * 68 + k];
    }
    g_G[j * 64 + k] = acc;
}

// ---------------------------------------------------------------------------
// Precompute 2: 12 blocks x 512 thr.
//  blocks 0-7: rv -> GT -> back-sub W -> W2 -> pack A chunk c=bid
//  blocks 8-11: rv (diag only) -> pack V n-chunk j=bid-8
// ---------------------------------------------------------------------------
#define PR_RV  0            // 64
#define PR_GT  64           // 64*65
#define PR_SW  4224         // 64*64
#define PR_SP  8320         // 64*68
#define PR_PV  64           // 128*65 (V path, overlaps GT/SW)
#define PR_FLOATS 12672

__global__ __launch_bounds__(512) void k_pack(const float* __restrict__ P) {
    extern __shared__ float sm[];
    int bid = blockIdx.x, tid = threadIdx.x, w = tid >> 5, lane = tid & 31;

    if (tid < 64) sm[PR_RV + tid] = rsqrtf(g_G[tid * 65]);
    __syncthreads();

    if (bid < 8) {
        int c = bid;
        // GT[i][jj] = 2*G[jj][i]*rv[i]*rv[jj]
        for (int idx = tid; idx < 4096; idx += 512) {
            int i = idx & 63, jj = idx >> 6;
            sm[PR_GT + i * 65 + jj] =
                2.f * g_G[jj * 64 + i] * sm[PR_RV + i] * sm[PR_RV + jj];
        }
        __syncthreads();
        // back-substitution: W = M^-1 (unit upper tri), 16 warps x 4 cols
        for (int k = w; k < 64; k += 16) {
            for (int i = lane; i < 64; i += 32)
                sm[PR_SW + k * 64 + i] = (i == k) ? 1.f : 0.f;
            __syncwarp();
            for (int i = k - 1; i >= 0; i--) {
                float s = 0.f;
                for (int jj = i + 1 + lane; jj <= k; jj += 32)
                    s += sm[PR_GT + i * 65 + jj] * sm[PR_SW + k * 64 + jj];
                #pragma unroll
                for (int o = 16; o; o >>= 1) s += __shfl_xor_sync(0xFFFFFFFFu, s, o);
                if (lane == 0) sm[PR_SW + k * 64 + i] = -s;
                __syncwarp();
            }
        }
        __syncthreads();
        // W2[jj][r] = 2 rv[jj] W[jj][r]  (into GT region)
        for (int idx = tid; idx < 4096; idx += 512) {
            int jj = idx >> 6, r = idx & 63;
            float v = (jj < r) ? 2.f * sm[PR_RV + jj] * sm[PR_SW + r * 64 + jj]
                               : (jj == r ? 2.f * sm[PR_RV + jj] : 0.f);
            sm[PR_GT + jj * 65 + r] = v;
        }
        // load P slab c
        for (int idx = tid; idx < 4096; idx += 512)
            sm[PR_SP + (idx >> 6) * 68 + (idx & 63)] = P[c * 4096 + idx];
        __syncthreads();
        // A'[r][kk] = sum_j P[kk][j] * W2[j][r]; pack bf16 hi/lo swizzled
        int rr = tid & 63, kb = (tid >> 6) << 3;
        float pacc[8] = {};
        #pragma unroll 4
        for (int jj = 0; jj < 64; jj++) {
            float wv = sm[PR_GT + jj * 65 + rr];
            #pragma unroll
            for (int e = 0; e < 8; e++)
                pacc[e] += sm[PR_SP + (kb + e) * 68 + jj] * wv;
        }
        #pragma unroll
        for (int e = 0; e < 8; e++) {
            float v = pacc[e];
            __nv_bfloat16 h = __float2bfloat16_rn(v);
            float lo = v - __bfloat162float(h);
            uint32_t off = c * 8192 + SWZ((uint32_t)(rr * 128 + (kb + e) * 2));
            *(__nv_bfloat16*)((char*)g_Abh + off) = h;
            *(__nv_bfloat16*)((char*)g_Abl + off) = __float2bfloat16_rn(lo);
        }
    } else {
        int jn = bid - 8;
        for (int idx = tid; idx < 8192; idx += 512)
            sm[PR_PV + (idx >> 6) * 65 + (idx & 63)] = P[jn * 8192 + idx];
        __syncthreads();
        for (int idx = tid; idx < 8192; idx += 512) {
            int n = idx >> 6, r = idx & 63;
            float v = sm[PR_PV + n * 65 + r] * sm[PR_RV + r];
            __nv_bfloat16 h = __float2bfloat16_rn(v);
            float lo = v - __bfloat162float(h);
            uint32_t off = jn * 16384 + SWZ((uint32_t)(n * 128 + r * 2));
            *(__nv_bfloat16*)((char*)g_Vbh + off) = h;
            *(__nv_bfloat16*)((char*)g_Vbl + off) = __float2bfloat16_rn(lo);
        }
    }
}

// ---------------------------------------------------------------------------
// Main kernel. X never touches smem (direct fragment loads + register convert).
// smem (96KB, 2 CTA/SM):
//   [0,     16384)  A ping
//   [16384, 32768)  A pong
//   [32768, 65536)  V buffer 0 (hi 16K + lo 16K)   j=0, then j=2
//   [65536, 98304)  V buffer 1 (hi 16K + lo 16K)   j=1, then j=3
// ---------------------------------------------------------------------------
#define OFF_A0  0
#define OFF_A1  16384
#define OFF_VB0 32768
#define OFF_VB1 65536
#define SMEM_BYTES 98304

__global__ __launch_bounds__(NTHREADS, 2) void k_gemm(const float* __restrict__ x,
                                                      float* __restrict__ out,
                                                      const float* __restrict__ sldj,
                                                      float* __restrict__ outSldj) {
    extern __shared__ char smem[];
    uint32_t sb = smem_to_u32(smem);

    int tid = threadIdx.x, wid = tid >> 5, lane = tid & 31;
    int m0 = blockIdx.x * TM;
    int mw = wid << 4;

    uint32_t lrow = lane & 15;
    uint32_t lcolb = (lane >> 4) << 4;
    uint32_t xw = (lrow & 7) << 4;

    // X fragment pointers: lane covers rows fr, fr+8; col pair fc
    int fr = lane >> 2, fc = (lane & 3) << 1;
    const float* px0 = x + (size_t)(m0 + mw + fr) * Dv + fc;
    const float* px1 = px0 + 8 * Dv;

    auto issueA = [&](int c, uint32_t buf) {
        const char* srch = (const char*)g_Abh + c * 8192;
        const char* srcl = (const char*)g_Abl + c * 8192;
        for (int idx = tid; idx < 512; idx += NTHREADS) {
            cpasync16(buf + idx * 16, srch + idx * 16);
            cpasync16(buf + 8192 + idx * 16, srcl + idx * 16);
        }
    };
    auto issueV = [&](int j, uint32_t buf) {     // hi at buf, lo at buf+16K
        const char* srch = (const char*)g_Vbh + j * 16384;
        const char* srcl = (const char*)g_Vbl + j * 16384;
        for (int idx = tid; idx < 1024; idx += NTHREADS) {
            cpasync16(buf + idx * 16, srch + idx * 16);
            cpasync16(buf + 16384 + idx * 16, srcl + idx * 16);
        }
    };

    // prologue: V0, V1, A0 in one group
    issueV(0, sb + OFF_VB0);
    issueV(1, sb + OFF_VB1);
    issueA(0, sb + OFF_A0);
    CP_COMMIT();

    // chunk 0: load X fragments + convert to bf16 hi/lo in registers
    float2 raw[16];
    #pragma unroll
    for (int ks = 0; ks < 4; ks++) {
        raw[ks * 4 + 0] = *(const float2*)(px0 + ks * 16);
        raw[ks * 4 + 1] = *(const float2*)(px1 + ks * 16);
        raw[ks * 4 + 2] = *(const float2*)(px0 + ks * 16 + 8);
        raw[ks * 4 + 3] = *(const float2*)(px1 + ks * 16 + 8);
    }
    uint32_t xh[4][4], xl[4][4];
    #pragma unroll
    for (int q = 0; q < 16; q++) {
        uint32_t h = cvt2(raw[q].x, raw[q].y);
        xh[q >> 2][q & 3] = h;
        xl[q >> 2][q & 3] = cvt2(raw[q].x - bl(h), raw[q].y - bh(h));
    }

    float acc[8][4];
    #pragma unroll
    for (int i = 0; i < 8; i++)
        acc[i][0] = acc[i][1] = acc[i][2] = acc[i][3] = 0.f;

    // ================= Phase 1: Y = X A  (8 k-chunks of 64) =================
    for (int c = 0; c < 8; c++) {
        CP_WAIT(0);
        __syncthreads();                 // A(c) visible; prior MMA reads done
        if (c < 7) {
            issueA(c + 1, sb + (((c + 1) & 1) ? OFF_A1 : OFF_A0));
            CP_COMMIT();
            int off = (c + 1) * 64;
            #pragma unroll
            for (int ks = 0; ks < 4; ks++) {
                raw[ks * 4 + 0] = *(const float2*)(px0 + off + ks * 16);
                raw[ks * 4 + 1] = *(const float2*)(px1 + off + ks * 16);
                raw[ks * 4 + 2] = *(const float2*)(px0 + off + ks * 16 + 8);
                raw[ks * 4 + 3] = *(const float2*)(px1 + off + ks * 16 + 8);
            }
        }
        uint32_t bufAh = sb + ((c & 1) ? OFF_A1 : OFF_A0);
        uint32_t bufAl = bufAh + 8192;
        #pragma unroll
        for (int ks = 0; ks < 4; ks++) {
            uint32_t ic = (lcolb + ks * 32) ^ xw;
            #pragma unroll
            for (int p = 0; p < 4; p++) {
                uint32_t ro = (lrow + p * 16) * 128;
                uint32_t bhr[4], blr[4];
                ldsm4(bhr, bufAh + ro + ic);
                ldsm4(blr, bufAl + ro + ic);
                mma16816(acc[2 * p],     xh[ks], bhr[0], bhr[2]);
                mma16816(acc[2 * p],     xh[ks], blr[0], blr[2]);
                mma16816(acc[2 * p],     xl[ks], bhr[0], bhr[2]);
                mma16816(acc[2 * p + 1], xh[ks], bhr[1], bhr[3]);
                mma16816(acc[2 * p + 1], xh[ks], blr[1], blr[3]);
                mma16816(acc[2 * p + 1], xl[ks], bhr[1], bhr[3]);
            }
        }
        if (c < 7) {
            #pragma unroll
            for (int q = 0; q < 16; q++) {
                uint32_t h = cvt2(raw[q].x, raw[q].y);
                xh[q >> 2][q & 3] = h;
                xl[q >> 2][q & 3] = cvt2(raw[q].x - bl(h), raw[q].y - bh(h));
            }
        }
    }

    // ======= Y: register repack acc (C-frag) -> phase-2 A-frags (hi/lo) =====
    uint32_t yh[4][4], yl[4][4];
    #pragma unroll
    for (int kb = 0; kb < 4; kb++) {
        uint32_t h;
        h = cvt2(acc[2*kb][0],   acc[2*kb][1]);   yh[kb][0] = h;
        yl[kb][0] = cvt2(acc[2*kb][0] - bl(h),    acc[2*kb][1] - bh(h));
        h = cvt2(acc[2*kb][2],   acc[2*kb][3]);   yh[kb][1] = h;
        yl[kb][1] = cvt2(acc[2*kb][2] - bl(h),    acc[2*kb][3] - bh(h));
        h = cvt2(acc[2*kb+1][0], acc[2*kb+1][1]); yh[kb][2] = h;
        yl[kb][2] = cvt2(acc[2*kb+1][0] - bl(h),  acc[2*kb+1][1] - bh(h));
        h = cvt2(acc[2*kb+1][2], acc[2*kb+1][3]); yh[kb][3] = h;
        yl[kb][3] = cvt2(acc[2*kb+1][2] - bl(h),  acc[2*kb+1][3] - bh(h));
    }

    // ================= Phase 2: Z = Y V^T, out = X - Z  (4 n-chunks) ========
    #pragma unroll
    for (int j = 0; j < 4; j++) {
        if (j == 2) { CP_WAIT(1); __syncthreads(); }   // V2 ready
        if (j == 3) { CP_WAIT(0); __syncthreads(); }   // V3 ready
        uint32_t bufVh = sb + ((j & 1) ? OFF_VB1 : OFF_VB0);
        uint32_t bufVl = bufVh + 16384;

        float z[16][4];
        #pragma unroll
        for (int i = 0; i < 16; i++)
            z[i][0] = z[i][1] = z[i][2] = z[i][3] = 0.f;

        #pragma unroll
        for (int ks = 0; ks < 4; ks++) {
            uint32_t ic = (lcolb + ks * 32) ^ xw;
            #pragma unroll
            for (int p = 0; p < 8; p++) {
                uint32_t ro = (lrow + p * 16) * 128;
                uint32_t bhr[4], blr[4];
                ldsm4(bhr, bufVh + ro + ic);
                ldsm4(blr, bufVl + ro + ic);
                mma16816(z[2 * p],     yh[ks], bhr[0], bhr[2]);
                mma16816(z[2 * p],     yh[ks], blr[0], blr[2]);
                mma16816(z[2 * p],     yl[ks], bhr[0], bhr[2]);
                mma16816(z[2 * p + 1], yh[ks], bhr[1], bhr[3]);
                mma16816(z[2 * p + 1], yh[ks], blr[1], blr[3]);
                mma16816(z[2 * p + 1], yl[ks], bhr[1], bhr[3]);
            }
        }
        if (j == 0) { __syncthreads(); issueV(2, sb + OFF_VB0); CP_COMMIT(); }
        if (j == 1) { __syncthreads(); issueV(3, sb + OFF_VB1); CP_COMMIT(); }

        // epilogue: out = x - z (fragment-mapped float2; x re-read hits L2)
        int r0 = m0 + mw + (lane >> 2);
        const float* x0p = x + (size_t)r0 * Dv;
        const float* x1p = x0p + 8 * Dv;
        float* o0 = out + (size_t)r0 * Dv;
        float* o1 = o0 + 8 * Dv;
        int cbase = (j << 7) + ((lane & 3) << 1);
        #pragma unroll
        for (int nt = 0; nt < 16; nt++) {
            int cc = cbase + nt * 8;
            float2 a0 = *(const float2*)(x0p + cc);
            float2 a1 = *(const float2*)(x1p + cc);
            float2 w0 = make_float2(a0.x - z[nt][0], a0.y - z[nt][1]);
            float2 w1 = make_float2(a1.x - z[nt][2], a1.y - z[nt][3]);
            *(float2*)(o0 + cc) = w0;
            *(float2*)(o1 + cc) = w1;
        }
    }

    if (outSldj != nullptr && tid < TM) {
        outSldj[m0 + tid] = sldj[m0 + tid];
    }
}

extern "C" void kernel_launch(void* const* d_in, const int* in_sizes, int n_in,
                              void* d_out, int out_size) {
    const float* x    = (const float*)d_in[0];   // (B, D)
    const float* sldj = (const float*)d_in[1];   // (B,)
    const float* P    = (const float*)d_in[2];   // (D, R)
    int BD = in_sizes[0];
    int Bn = in_sizes[1];
    (void)n_in;
    float* out = (float*)d_out;
    float* osl = (out_size >= BD + Bn) ? (out + BD) : nullptr;

    k_gram<<<16, 256>>>(P);
    cudaFuncSetAttribute(k_pack, cudaFuncAttributeMaxDynamicSharedMemorySize,
                         PR_FLOATS * 4);
    k_pack<<<12, 512, PR_FLOATS * 4>>>(P);

    cudaFuncSetAttribute(k_gemm, cudaFuncAttributeMaxDynamicSharedMemorySize, SMEM_BYTES);
    k_gemm<<<Bn / TM, NTHREADS, SMEM_BYTES>>>(x, out, sldj, osl);
}

// round 10
// speedup vs baseline: 1.3022x; 1.0838x over previous
#include <cuda_runtime.h>
#include <cuda_bf16.h>
#include <cstdint>

#define Dv 512
#define Rv 64
#define TM 128
#define NTHREADS 256

// ---------------------------------------------------------------------------
// Device scratch
// ---------------------------------------------------------------------------
__device__ float g_G[64 * 64];    // Gram matrix G = P^T P
// Pre-packed bf16 hi/lo operand tiles, 128B rows, SW128-swizzled
__device__ __align__(16) __nv_bfloat16 g_Abh[8 * 64 * 64];   // chunk c: [r][kk]
__device__ __align__(16) __nv_bfloat16 g_Abl[8 * 64 * 64];
__device__ __align__(16) __nv_bfloat16 g_Vbh[4 * 128 * 64];  // n-chunk j: [n][r]
__device__ __align__(16) __nv_bfloat16 g_Vbl[4 * 128 * 64];

// ---------------------------------------------------------------------------
// Helpers
// ---------------------------------------------------------------------------
#define SWZ(o) ((o) ^ (((o) >> 3) & 0x70))

__device__ __forceinline__ uint32_t smem_to_u32(const void* p) {
    uint32_t a;
    asm("{ .reg .u64 t; cvta.to.shared.u64 t, %1; cvt.u32.u64 %0, t; }" : "=r"(a) : "l"(p));
    return a;
}
__device__ __forceinline__ void ldsm4(uint32_t* r, uint32_t addr) {
    asm volatile("ldmatrix.sync.aligned.m8n8.x4.shared.b16 {%0,%1,%2,%3}, [%4];"
                 : "=r"(r[0]), "=r"(r[1]), "=r"(r[2]), "=r"(r[3]) : "r"(addr));
}
__device__ __forceinline__ void mma16816(float* c, const uint32_t* a,
                                         uint32_t b0, uint32_t b1) {
    asm volatile("mma.sync.aligned.m16n8k16.row.col.f32.bf16.bf16.f32 "
                 "{%0,%1,%2,%3}, {%4,%5,%6,%7}, {%8,%9}, {%0,%1,%2,%3};"
                 : "+f"(c[0]), "+f"(c[1]), "+f"(c[2]), "+f"(c[3])
                 : "r"(a[0]), "r"(a[1]), "r"(a[2]), "r"(a[3]), "r"(b0), "r"(b1));
}
__device__ __forceinline__ void sts128(uint32_t a, uint32_t x, uint32_t y,
                                       uint32_t z, uint32_t w) {
    asm volatile("st.shared.v4.b32 [%0], {%1,%2,%3,%4};"
                 :: "r"(a), "r"(x), "r"(y), "r"(z), "r"(w) : "memory");
}
__device__ __forceinline__ float4 lds128(uint32_t a) {
    float4 v;
    asm volatile("ld.shared.v4.f32 {%0,%1,%2,%3}, [%4];"
                 : "=f"(v.x), "=f"(v.y), "=f"(v.z), "=f"(v.w) : "r"(a));
    return v;
}
__device__ __forceinline__ void cpasync16(uint32_t dst, const void* src) {
    asm volatile("cp.async.cg.shared.global [%0], [%1], 16;"
                 :: "r"(dst), "l"(src) : "memory");
}
#define CP_COMMIT() asm volatile("cp.async.commit_group;" ::: "memory")
#define CP_WAIT(N)  asm volatile("cp.async.wait_group %0;" :: "n"(N) : "memory")

__device__ __forceinline__ uint32_t cvt2(float f0, float f1) {
    uint32_t r;
    asm("cvt.rn.bf16x2.f32 %0, %1, %2;" : "=r"(r) : "f"(f1), "f"(f0));
    return r;
}
__device__ __forceinline__ float bl(uint32_t h) { return __uint_as_float(h << 16); }
__device__ __forceinline__ float bh(uint32_t h) { return __uint_as_float(h & 0xFFFF0000u); }

// ---------------------------------------------------------------------------
// Precompute 1: Gram row per block. 64 blocks x 256 thr, direct from global
// (L2-hot), 4-way d-split, smem reduce. No streaming barriers.
// ---------------------------------------------------------------------------
__global__ __launch_bounds__(256) void k_gram(const float* __restrict__ P) {
    __shared__ float red[4][64];
    int j = blockIdx.x;
    int k = threadIdx.x & 63, g = threadIdx.x >> 6;     // 4 d-groups of 128
    const float* p = P + g * 128 * 64;
    float a0 = 0.f, a1 = 0.f, a2 = 0.f, a3 = 0.f;
    #pragma unroll 4
    for (int d = 0; d < 128; d += 4) {
        a0 += __ldg(p + (d + 0) * 64 + j) * __ldg(p + (d + 0) * 64 + k);
        a1 += __ldg(p + (d + 1) * 64 + j) * __ldg(p + (d + 1) * 64 + k);
        a2 += __ldg(p + (d + 2) * 64 + j) * __ldg(p + (d + 2) * 64 + k);
        a3 += __ldg(p + (d + 3) * 64 + j) * __ldg(p + (d + 3) * 64 + k);
    }
    red[g][k] = (a0 + a1) + (a2 + a3);
    __syncthreads();
    if (g == 0)
        g_G[j * 64 + k] = (red[0][k] + red[1][k]) + (red[2][k] + red[3][k]);
}

// ---------------------------------------------------------------------------
// Precompute 2: 12 blocks x 512 thr.
//  blocks 0-7: rv -> GT -> back-sub W -> W2 -> pack A chunk c=bid
//  blocks 8-11: rv (diag only) -> pack V n-chunk j=bid-8
// ---------------------------------------------------------------------------
#define PR_RV  0            // 64
#define PR_GT  64           // 64*65
#define PR_SW  4224         // 64*64
#define PR_SP  8320         // 64*68
#define PR_PV  64           // 128*65 (V path, overlaps GT/SW)
#define PR_FLOATS 12672

__global__ __launch_bounds__(512) void k_pack(const float* __restrict__ P) {
    extern __shared__ float sm[];
    int bid = blockIdx.x, tid = threadIdx.x, w = tid >> 5, lane = tid & 31;

    if (tid < 64) sm[PR_RV + tid] = rsqrtf(g_G[tid * 65]);
    __syncthreads();

    if (bid < 8) {
        int c = bid;
        // GT[i][jj] = 2*G[jj][i]*rv[i]*rv[jj]
        for (int idx = tid; idx < 4096; idx += 512) {
            int i = idx & 63, jj = idx >> 6;
            sm[PR_GT + i * 65 + jj] =
                2.f * g_G[jj * 64 + i] * sm[PR_RV + i] * sm[PR_RV + jj];
        }
        __syncthreads();
        // back-substitution: W = M^-1 (unit upper tri), 16 warps x 4 cols
        for (int k = w; k < 64; k += 16) {
            for (int i = lane; i < 64; i += 32)
                sm[PR_SW + k * 64 + i] = (i == k) ? 1.f : 0.f;
            __syncwarp();
            for (int i = k - 1; i >= 0; i--) {
                float s = 0.f;
                for (int jj = i + 1 + lane; jj <= k; jj += 32)
                    s += sm[PR_GT + i * 65 + jj] * sm[PR_SW + k * 64 + jj];
                #pragma unroll
                for (int o = 16; o; o >>= 1) s += __shfl_xor_sync(0xFFFFFFFFu, s, o);
                if (lane == 0) sm[PR_SW + k * 64 + i] = -s;
                __syncwarp();
            }
        }
        __syncthreads();
        // W2[jj][r] = 2 rv[jj] W[jj][r]  (into GT region)
        for (int idx = tid; idx < 4096; idx += 512) {
            int jj = idx >> 6, r = idx & 63;
            float v = (jj < r) ? 2.f * sm[PR_RV + jj] * sm[PR_SW + r * 64 + jj]
                               : (jj == r ? 2.f * sm[PR_RV + jj] : 0.f);
            sm[PR_GT + jj * 65 + r] = v;
        }
        // load P slab c
        for (int idx = tid; idx < 4096; idx += 512)
            sm[PR_SP + (idx >> 6) * 68 + (idx & 63)] = P[c * 4096 + idx];
        __syncthreads();
        // A'[r][kk] = sum_j P[kk][j] * W2[j][r]; pack bf16 hi/lo swizzled
        int rr = tid & 63, kb = (tid >> 6) << 3;
        float pacc[8] = {};
        #pragma unroll 4
        for (int jj = 0; jj < 64; jj++) {
            float wv = sm[PR_GT + jj * 65 + rr];
            #pragma unroll
            for (int e = 0; e < 8; e++)
                pacc[e] += sm[PR_SP + (kb + e) * 68 + jj] * wv;
        }
        #pragma unroll
        for (int e = 0; e < 8; e++) {
            float v = pacc[e];
            __nv_bfloat16 h = __float2bfloat16_rn(v);
            float lo = v - __bfloat162float(h);
            uint32_t off = c * 8192 + SWZ((uint32_t)(rr * 128 + (kb + e) * 2));
            *(__nv_bfloat16*)((char*)g_Abh + off) = h;
            *(__nv_bfloat16*)((char*)g_Abl + off) = __float2bfloat16_rn(lo);
        }
    } else {
        int jn = bid - 8;
        for (int idx = tid; idx < 8192; idx += 512)
            sm[PR_PV + (idx >> 6) * 65 + (idx & 63)] = P[jn * 8192 + idx];
        __syncthreads();
        for (int idx = tid; idx < 8192; idx += 512) {
            int n = idx >> 6, r = idx & 63;
            float v = sm[PR_PV + n * 65 + r] * sm[PR_RV + r];
            __nv_bfloat16 h = __float2bfloat16_rn(v);
            float lo = v - __bfloat162float(h);
            uint32_t off = jn * 16384 + SWZ((uint32_t)(n * 128 + r * 2));
            *(__nv_bfloat16*)((char*)g_Vbh + off) = h;
            *(__nv_bfloat16*)((char*)g_Vbl + off) = __float2bfloat16_rn(lo);
        }
    }
}

// ---------------------------------------------------------------------------
// Main kernel — R8 structure verbatim (measured 135.4us).
// smem (96KB, 2 CTA/SM):
//   [0,     32768)  stage: raw fp32 X chunk (cp.async) / V buffers 0,3
//   [32768, 65536)  Xh/Xl bf16                          / V buffer 2
//   [65536, 98304)  A ping/pong 16K each                / V buffer 1
// ---------------------------------------------------------------------------
#define OFF_STAGE 0
#define OFF_XH    32768
#define OFF_XL    49152
#define OFF_A0    65536
#define OFF_A1    81920
#define SMEM_BYTES 98304

__global__ __launch_bounds__(NTHREADS, 2) void k_gemm(const float* __restrict__ x,
                                                      float* __restrict__ out,
                                                      const float* __restrict__ sldj,
                                                      float* __restrict__ outSldj) {
    extern __shared__ char smem[];
    uint32_t sb = smem_to_u32(smem);
    const uint32_t sStage = sb + OFF_STAGE;
    const uint32_t sXh = sb + OFF_XH, sXl = sb + OFF_XL;

    int tid = threadIdx.x, wid = tid >> 5, lane = tid & 31;
    int m0 = blockIdx.x * TM;
    int mw = wid << 4;

    uint32_t lrow = lane & 15;
    uint32_t lcolb = (lane >> 4) << 4;
    uint32_t xw = (lrow & 7) << 4;
    uint32_t arowb = (mw + lrow) * 128;

    auto issueX = [&](int c) {
        for (int idx = tid; idx < 2048; idx += NTHREADS) {
            int r = idx >> 4, i = idx & 15;
            uint32_t dst = sStage + r * 256 + (((uint32_t)(i * 16)) ^ ((r & 7) << 5));
            const char* src = (const char*)(x + (size_t)(m0 + r) * Dv + c * 64 + i * 4);
            cpasync16(dst, src);
        }
    };
    auto issueA = [&](int c, uint32_t buf) {
        const char* srch = (const char*)g_Abh + c * 8192;
        const char* srcl = (const char*)g_Abl + c * 8192;
        for (int idx = tid; idx < 512; idx += NTHREADS) {
            cpasync16(buf + idx * 16, srch + idx * 16);
            cpasync16(buf + 8192 + idx * 16, srcl + idx * 16);
        }
    };
    auto issueV = [&](int j, uint32_t bufh, uint32_t bufl) {
        const char* srch = (const char*)g_Vbh + j * 16384;
        const char* srcl = (const char*)g_Vbl + j * 16384;
        for (int idx = tid; idx < 1024; idx += NTHREADS) {
            cpasync16(bufh + idx * 16, srch + idx * 16);
            cpasync16(bufl + idx * 16, srcl + idx * 16);
        }
    };

    float acc[8][4];
    #pragma unroll
    for (int i = 0; i < 8; i++)
        acc[i][0] = acc[i][1] = acc[i][2] = acc[i][3] = 0.f;

    issueX(0); issueA(0, sb + OFF_A0); CP_COMMIT();

    // ================= Phase 1: Y = X A  (8 k-chunks of 64) =================
    for (int c = 0; c < 8; c++) {
        CP_WAIT(0);
        __syncthreads();
        // convert stage -> Xh/Xl (bf16 hi/lo, SW128)
        #pragma unroll
        for (int p = 0; p < 4; p++) {
            int it = tid + p * NTHREADS;
            int row = it >> 3, g = it & 7;
            uint32_t sa = sStage + row * 256 + (((uint32_t)(g * 32)) ^ ((row & 7) << 5));
            float4 v0 = lds128(sa);
            float4 v1 = lds128(sa + 16);
            float f[8] = {v0.x, v0.y, v0.z, v0.w, v1.x, v1.y, v1.z, v1.w};
            uint32_t H[4], L[4];
            #pragma unroll
            for (int q = 0; q < 4; q++) {
                uint32_t h = cvt2(f[2 * q], f[2 * q + 1]);
                H[q] = h;
                L[q] = cvt2(f[2 * q] - bl(h), f[2 * q + 1] - bh(h));
            }
            uint32_t ad = row * 128 + (((uint32_t)(g * 16)) ^ ((row & 7) << 4));
            sts128(sXh + ad, H[0], H[1], H[2], H[3]);
            sts128(sXl + ad, L[0], L[1], L[2], L[3]);
        }
        __syncthreads();
        if (c < 7) {
            issueX(c + 1);
            issueA(c + 1, sb + ((c + 1) & 1 ? OFF_A1 : OFF_A0));
            CP_COMMIT();
        } else {
            issueV(0, sStage, sStage + 16384);   // stage free after conversion
            CP_COMMIT();
        }
        uint32_t bufAh = sb + ((c & 1) ? OFF_A1 : OFF_A0);
        uint32_t bufAl = bufAh + 8192;
        #pragma unroll
        for (int ks = 0; ks < 4; ks++) {
            uint32_t ic = (lcolb + ks * 32) ^ xw;
            uint32_t ah[4], al[4];
            ldsm4(ah, sXh + arowb + ic);
            ldsm4(al, sXl + arowb + ic);
            #pragma unroll
            for (int p = 0; p < 4; p++) {
                uint32_t ro = (lrow + p * 16) * 128;
                uint32_t bhr[4], blr[4];
                ldsm4(bhr, bufAh + ro + ic);
                ldsm4(blr, bufAl + ro + ic);
                mma16816(acc[2 * p],     ah, bhr[0], bhr[2]);
                mma16816(acc[2 * p],     ah, blr[0], blr[2]);
                mma16816(acc[2 * p],     al, bhr[0], bhr[2]);
                mma16816(acc[2 * p + 1], ah, bhr[1], bhr[3]);
                mma16816(acc[2 * p + 1], ah, blr[1], blr[3]);
                mma16816(acc[2 * p + 1], al, bhr[1], bhr[3]);
            }
        }
    }
    __syncthreads();                       // MMA(7) done: A + X regions free
    issueV(1, sb + OFF_A0, sb + OFF_A1); CP_COMMIT();
    issueV(2, sXh, sXl);                 CP_COMMIT();

    // ======= Y: register repack acc (C-frag) -> phase-2 A-frags (hi/lo) =====
    uint32_t yh[4][4], yl[4][4];
    #pragma unroll
    for (int kb = 0; kb < 4; kb++) {
        uint32_t h;
        h = cvt2(acc[2*kb][0],   acc[2*kb][1]);   yh[kb][0] = h;
        yl[kb][0] = cvt2(acc[2*kb][0] - bl(h),    acc[2*kb][1] - bh(h));
        h = cvt2(acc[2*kb][2],   acc[2*kb][3]);   yh[kb][1] = h;
        yl[kb][1] = cvt2(acc[2*kb][2] - bl(h),    acc[2*kb][3] - bh(h));
        h = cvt2(acc[2*kb+1][0], acc[2*kb+1][1]); yh[kb][2] = h;
        yl[kb][2] = cvt2(acc[2*kb+1][0] - bl(h),  acc[2*kb+1][1] - bh(h));
        h = cvt2(acc[2*kb+1][2], acc[2*kb+1][3]); yh[kb][3] = h;
        yl[kb][3] = cvt2(acc[2*kb+1][2] - bl(h),  acc[2*kb+1][3] - bh(h));
    }

    // ================= Phase 2: Z = Y V^T, out = X - Z  (4 n-chunks) ========
    const uint32_t vhOff[4] = {OFF_STAGE, OFF_A0, OFF_XH, OFF_STAGE};
    const uint32_t vlOff[4] = {OFF_STAGE + 16384, OFF_A1, OFF_XL, OFF_STAGE + 16384};
    #pragma unroll
    for (int j = 0; j < 4; j++) {
        if (j <= 1) { CP_WAIT(2); } else if (j == 2) { CP_WAIT(1); } else { CP_WAIT(0); }
        __syncthreads();
        uint32_t bufVh = sb + vhOff[j], bufVl = sb + vlOff[j];

        float z[16][4];
        #pragma unroll
        for (int i = 0; i < 16; i++)
            z[i][0] = z[i][1] = z[i][2] = z[i][3] = 0.f;

        #pragma unroll
        for (int ks = 0; ks < 4; ks++) {
            uint32_t ic = (lcolb + ks * 32) ^ xw;
            #pragma unroll
            for (int p = 0; p < 8; p++) {
                uint32_t ro = (lrow + p * 16) * 128;
                uint32_t bhr[4], blr[4];
                ldsm4(bhr, bufVh + ro + ic);
                ldsm4(blr, bufVl + ro + ic);
                mma16816(z[2 * p],     yh[ks], bhr[0], bhr[2]);
                mma16816(z[2 * p],     yh[ks], blr[0], blr[2]);
                mma16816(z[2 * p],     yl[ks], bhr[0], bhr[2]);
                mma16816(z[2 * p + 1], yh[ks], bhr[1], bhr[3]);
                mma16816(z[2 * p + 1], yh[ks], blr[1], blr[3]);
                mma16816(z[2 * p + 1], yl[ks], bhr[1], bhr[3]);
            }
        }
        if (j == 0) {   // all warps done reading V0 -> stage free for V3
            __syncthreads();
            issueV(3, sStage, sStage + 16384);
            CP_COMMIT();
        }

        // epilogue: out = x - z (fragment-mapped float2; x re-read hits L2)
        int r0 = m0 + mw + (lane >> 2);
        const float* x0p = x + (size_t)r0 * Dv;
        const float* x1p = x0p + 8 * Dv;
        float* o0 = out + (size_t)r0 * Dv;
        float* o1 = o0 + 8 * Dv;
        int cbase = (j << 7) + ((lane & 3) << 1);
        #pragma unroll
        for (int nt = 0; nt < 16; nt++) {
            int cc = cbase + nt * 8;
            float2 a0 = *(const float2*)(x0p + cc);
            float2 a1 = *(const float2*)(x1p + cc);
            float2 w0 = make_float2(a0.x - z[nt][0], a0.y - z[nt][1]);
            float2 w1 = make_float2(a1.x - z[nt][2], a1.y - z[nt][3]);
            *(float2*)(o0 + cc) = w0;
            *(float2*)(o1 + cc) = w1;
        }
    }

    if (outSldj != nullptr && tid < TM) {
        outSldj[m0 + tid] = sldj[m0 + tid];
    }
}

extern "C" void kernel_launch(void* const* d_in, const int* in_sizes, int n_in,
                              void* d_out, int out_size) {
    const float* x    = (const float*)d_in[0];   // (B, D)
    const float* sldj = (const float*)d_in[1];   // (B,)
    const float* P    = (const float*)d_in[2];   // (D, R)
    int BD = in_sizes[0];
    int Bn = in_sizes[1];
    (void)n_in;
    float* out = (float*)d_out;
    float* osl = (out_size >= BD + Bn) ? (out + BD) : nullptr;

    k_gram<<<64, 256>>>(P);
    cudaFuncSetAttribute(k_pack, cudaFuncAttributeMaxDynamicSharedMemorySize,
                         PR_FLOATS * 4);
    k_pack<<<12, 512, PR_FLOATS * 4>>>(P);

    cudaFuncSetAttribute(k_gemm, cudaFuncAttributeMaxDynamicSharedMemorySize, SMEM_BYTES);
    k_gemm<<<Bn / TM, NTHREADS, SMEM_BYTES>>>(x, out, sldj, osl);
}

// round 11
// speedup vs baseline: 1.4899x; 1.1441x over previous
#include <cuda_runtime.h>
#include <cuda_bf16.h>
#include <cstdint>

#define Dv 512
#define Rv 64
#define TM 128
#define NTHREADS 256

// ---------------------------------------------------------------------------
// Device scratch
// ---------------------------------------------------------------------------
__device__ float g_G[64 * 64];    // Gram matrix G = P^T P (symmetric)
// Pre-packed bf16 hi/lo operand tiles, 128B rows, SW128-swizzled
__device__ __align__(16) __nv_bfloat16 g_Abh[8 * 64 * 64];   // chunk c: [r][kk]
__device__ __align__(16) __nv_bfloat16 g_Abl[8 * 64 * 64];
__device__ __align__(16) __nv_bfloat16 g_Vbh[4 * 128 * 64];  // n-chunk j: [n][r]
__device__ __align__(16) __nv_bfloat16 g_Vbl[4 * 128 * 64];

// ---------------------------------------------------------------------------
// Helpers
// ---------------------------------------------------------------------------
#define SWZ(o) ((o) ^ (((o) >> 3) & 0x70))

__device__ __forceinline__ uint32_t smem_to_u32(const void* p) {
    uint32_t a;
    asm("{ .reg .u64 t; cvta.to.shared.u64 t, %1; cvt.u32.u64 %0, t; }" : "=r"(a) : "l"(p));
    return a;
}
__device__ __forceinline__ void ldsm4(uint32_t* r, uint32_t addr) {
    asm volatile("ldmatrix.sync.aligned.m8n8.x4.shared.b16 {%0,%1,%2,%3}, [%4];"
                 : "=r"(r[0]), "=r"(r[1]), "=r"(r[2]), "=r"(r[3]) : "r"(addr));
}
__device__ __forceinline__ void mma16816(float* c, const uint32_t* a,
                                         uint32_t b0, uint32_t b1) {
    asm volatile("mma.sync.aligned.m16n8k16.row.col.f32.bf16.bf16.f32 "
                 "{%0,%1,%2,%3}, {%4,%5,%6,%7}, {%8,%9}, {%0,%1,%2,%3};"
                 : "+f"(c[0]), "+f"(c[1]), "+f"(c[2]), "+f"(c[3])
                 : "r"(a[0]), "r"(a[1]), "r"(a[2]), "r"(a[3]), "r"(b0), "r"(b1));
}
__device__ __forceinline__ void sts128(uint32_t a, uint32_t x, uint32_t y,
                                       uint32_t z, uint32_t w) {
    asm volatile("st.shared.v4.b32 [%0], {%1,%2,%3,%4};"
                 :: "r"(a), "r"(x), "r"(y), "r"(z), "r"(w) : "memory");
}
__device__ __forceinline__ float4 lds128(uint32_t a) {
    float4 v;
    asm volatile("ld.shared.v4.f32 {%0,%1,%2,%3}, [%4];"
                 : "=f"(v.x), "=f"(v.y), "=f"(v.z), "=f"(v.w) : "r"(a));
    return v;
}
__device__ __forceinline__ void cpasync16(uint32_t dst, const void* src) {
    asm volatile("cp.async.cg.shared.global [%0], [%1], 16;"
                 :: "r"(dst), "l"(src) : "memory");
}
#define CP_COMMIT() asm volatile("cp.async.commit_group;" ::: "memory")
#define CP_WAIT(N)  asm volatile("cp.async.wait_group %0;" :: "n"(N) : "memory")

__device__ __forceinline__ uint32_t cvt2(float f0, float f1) {
    uint32_t r;
    asm("cvt.rn.bf16x2.f32 %0, %1, %2;" : "=r"(r) : "f"(f1), "f"(f0));
    return r;
}
__device__ __forceinline__ float bl(uint32_t h) { return __uint_as_float(h << 16); }
__device__ __forceinline__ float bh(uint32_t h) { return __uint_as_float(h & 0xFFFF0000u); }

// ---------------------------------------------------------------------------
// Precompute 1: Gram row per block, 8-way MLP. 64 blocks x 256 thr.
// ---------------------------------------------------------------------------
__global__ __launch_bounds__(256) void k_gram(const float* __restrict__ P) {
    __shared__ float red[4][64];
    int j = blockIdx.x;
    int k = threadIdx.x & 63, g = threadIdx.x >> 6;     // 4 d-groups of 128
    const float* p = P + g * 128 * 64;
    float a[8] = {};
    #pragma unroll 2
    for (int d = 0; d < 128; d += 8) {
        #pragma unroll
        for (int e = 0; e < 8; e++)
            a[e] += __ldg(p + (d + e) * 64 + j) * __ldg(p + (d + e) * 64 + k);
    }
    red[g][k] = ((a[0] + a[1]) + (a[2] + a[3])) + ((a[4] + a[5]) + (a[6] + a[7]));
    __syncthreads();
    if (g == 0)
        g_G[j * 64 + k] = (red[0][k] + red[1][k]) + (red[2][k] + red[3][k]);
}

// ---------------------------------------------------------------------------
// Precompute 2: 12 blocks x 512 thr.
//  blocks 0-7: rv -> M -> SCAN back-sub W -> W2 -> pack A chunk c=bid
//  blocks 8-11: rv (diag only) -> pack V n-chunk j=bid-8
// smem float offsets:
// ---------------------------------------------------------------------------
#define PR_RV  0            // 64
#define PR_M   64           // 64*65  sM[i][l] = 2*Ghat[i][l]
#define PR_W2  4224         // 64*65  W2[jj][r]
#define PR_SP  8384         // 64*68  P slab
#define PR_PV  64           // 128*65 (V path, overlaps M/W2)
#define PR_FLOATS 12736

__global__ __launch_bounds__(512) void k_pack(const float* __restrict__ P) {
    extern __shared__ float sm[];
    int bid = blockIdx.x, tid = threadIdx.x, w = tid >> 5, lane = tid & 31;

    if (tid < 64) sm[PR_RV + tid] = rsqrtf(g_G[tid * 65]);
    __syncthreads();

    if (bid < 8) {
        int c = bid;
        // sM[i][l] = 2*G[i][l]*rv[i]*rv[l]  (G symmetric -> coalesced in l)
        for (int idx = tid; idx < 4096; idx += 512) {
            int i = idx >> 6, l = idx & 63;
            sm[PR_M + i * 65 + l] = 2.f * g_G[idx] * sm[PR_RV + i] * sm[PR_RV + l];
        }
        // stage P slab c (independent)
        for (int idx = tid; idx < 4096; idx += 512)
            sm[PR_SP + (idx >> 6) * 68 + (idx & 63)] = P[c * 4096 + idx];
        __syncthreads();

        // ---- scan back-substitution: warp w solves cols {w,w+16,w+32,w+48} --
        // Solve M wcol = e_c (M unit upper tri). Row l owned by lane (l&31),
        // slot (l>>5). S = running sum of M[l][j]*w[j] over processed j>i.
        {
            float S0[4] = {0.f, 0.f, 0.f, 0.f};
            float S1[4] = {0.f, 0.f, 0.f, 0.f};
            float wv0[4] = {0.f, 0.f, 0.f, 0.f};
            float wv1[4] = {0.f, 0.f, 0.f, 0.f};
            for (int i = 63; i >= 0; --i) {
                float m0 = sm[PR_M + i * 65 + lane];
                float m1 = sm[PR_M + i * 65 + lane + 32];
                #pragma unroll
                for (int q = 0; q < 4; q++) {
                    int cq = w + 16 * q;
                    float sown = (i < 32) ? S0[q] : S1[q];
                    float s_i = __shfl_sync(0xFFFFFFFFu, sown, i & 31);
                    float wi = (i > cq) ? 0.f : ((i == cq) ? 1.f : -s_i);
                    if (lane == i)      wv0[q] = wi;
                    if (lane + 32 == i) wv1[q] = wi;
                    if (lane < i)       S0[q] += m0 * wi;
                    if (lane + 32 < i)  S1[q] += m1 * wi;
                }
            }
            // W2[jj][r] = 2*rv[jj]*W[jj][r]
            #pragma unroll
            for (int q = 0; q < 4; q++) {
                int cq = w + 16 * q;
                sm[PR_W2 + lane * 65 + cq]        = 2.f * sm[PR_RV + lane] * wv0[q];
                sm[PR_W2 + (lane + 32) * 65 + cq] = 2.f * sm[PR_RV + lane + 32] * wv1[q];
            }
        }
        __syncthreads();

        // A'[r][kk] = sum_j P[kk][j] * W2[j][r]; pack bf16 hi/lo swizzled
        int rr = tid & 63, kb = (tid >> 6) << 3;
        float pacc[8] = {};
        #pragma unroll 4
        for (int jj = 0; jj < 64; jj++) {
            float wv = sm[PR_W2 + jj * 65 + rr];
            #pragma unroll
            for (int e = 0; e < 8; e++)
                pacc[e] += sm[PR_SP + (kb + e) * 68 + jj] * wv;
        }
        #pragma unroll
        for (int e = 0; e < 8; e++) {
            float v = pacc[e];
            __nv_bfloat16 h = __float2bfloat16_rn(v);
            float lo = v - __bfloat162float(h);
            uint32_t off = c * 8192 + SWZ((uint32_t)(rr * 128 + (kb + e) * 2));
            *(__nv_bfloat16*)((char*)g_Abh + off) = h;
            *(__nv_bfloat16*)((char*)g_Abl + off) = __float2bfloat16_rn(lo);
        }
    } else {
        int jn = bid - 8;
        for (int idx = tid; idx < 8192; idx += 512)
            sm[PR_PV + (idx >> 6) * 65 + (idx & 63)] = P[jn * 8192 + idx];
        __syncthreads();
        for (int idx = tid; idx < 8192; idx += 512) {
            int n = idx >> 6, r = idx & 63;
            float v = sm[PR_PV + n * 65 + r] * sm[PR_RV + r];
            __nv_bfloat16 h = __float2bfloat16_rn(v);
            float lo = v - __bfloat162float(h);
            uint32_t off = jn * 16384 + SWZ((uint32_t)(n * 128 + r * 2));
            *(__nv_bfloat16*)((char*)g_Vbh + off) = h;
            *(__nv_bfloat16*)((char*)g_Vbl + off) = __float2bfloat16_rn(lo);
        }
    }
}

// ---------------------------------------------------------------------------
// Main kernel — R8 structure verbatim (measured 135.4us, do not touch).
// smem (96KB, 2 CTA/SM):
//   [0,     32768)  stage: raw fp32 X chunk (cp.async) / V buffers 0,3
//   [32768, 65536)  Xh/Xl bf16                          / V buffer 2
//   [65536, 98304)  A ping/pong 16K each                / V buffer 1
// ---------------------------------------------------------------------------
#define OFF_STAGE 0
#define OFF_XH    32768
#define OFF_XL    49152
#define OFF_A0    65536
#define OFF_A1    81920
#define SMEM_BYTES 98304

__global__ __launch_bounds__(NTHREADS, 2) void k_gemm(const float* __restrict__ x,
                                                      float* __restrict__ out,
                                                      const float* __restrict__ sldj,
                                                      float* __restrict__ outSldj) {
    extern __shared__ char smem[];
    uint32_t sb = smem_to_u32(smem);
    const uint32_t sStage = sb + OFF_STAGE;
    const uint32_t sXh = sb + OFF_XH, sXl = sb + OFF_XL;

    int tid = threadIdx.x, wid = tid >> 5, lane = tid & 31;
    int m0 = blockIdx.x * TM;
    int mw = wid << 4;

    uint32_t lrow = lane & 15;
    uint32_t lcolb = (lane >> 4) << 4;
    uint32_t xw = (lrow & 7) << 4;
    uint32_t arowb = (mw + lrow) * 128;

    auto issueX = [&](int c) {
        for (int idx = tid; idx < 2048; idx += NTHREADS) {
            int r = idx >> 4, i = idx & 15;
            uint32_t dst = sStage + r * 256 + (((uint32_t)(i * 16)) ^ ((r & 7) << 5));
            const char* src = (const char*)(x + (size_t)(m0 + r) * Dv + c * 64 + i * 4);
            cpasync16(dst, src);
        }
    };
    auto issueA = [&](int c, uint32_t buf) {
        const char* srch = (const char*)g_Abh + c * 8192;
        const char* srcl = (const char*)g_Abl + c * 8192;
        for (int idx = tid; idx < 512; idx += NTHREADS) {
            cpasync16(buf + idx * 16, srch + idx * 16);
            cpasync16(buf + 8192 + idx * 16, srcl + idx * 16);
        }
    };
    auto issueV = [&](int j, uint32_t bufh, uint32_t bufl) {
        const char* srch = (const char*)g_Vbh + j * 16384;
        const char* srcl = (const char*)g_Vbl + j * 16384;
        for (int idx = tid; idx < 1024; idx += NTHREADS) {
            cpasync16(bufh + idx * 16, srch + idx * 16);
            cpasync16(bufl + idx * 16, srcl + idx * 16);
        }
    };

    float acc[8][4];
    #pragma unroll
    for (int i = 0; i < 8; i++)
        acc[i][0] = acc[i][1] = acc[i][2] = acc[i][3] = 0.f;

    issueX(0); issueA(0, sb + OFF_A0); CP_COMMIT();

    // ================= Phase 1: Y = X A  (8 k-chunks of 64) =================
    for (int c = 0; c < 8; c++) {
        CP_WAIT(0);
        __syncthreads();
        // convert stage -> Xh/Xl (bf16 hi/lo, SW128)
        #pragma unroll
        for (int p = 0; p < 4; p++) {
            int it = tid + p * NTHREADS;
            int row = it >> 3, g = it & 7;
            uint32_t sa = sStage + row * 256 + (((uint32_t)(g * 32)) ^ ((row & 7) << 5));
            float4 v0 = lds128(sa);
            float4 v1 = lds128(sa + 16);
            float f[8] = {v0.x, v0.y, v0.z, v0.w, v1.x, v1.y, v1.z, v1.w};
            uint32_t H[4], L[4];
            #pragma unroll
            for (int q = 0; q < 4; q++) {
                uint32_t h = cvt2(f[2 * q], f[2 * q + 1]);
                H[q] = h;
                L[q] = cvt2(f[2 * q] - bl(h), f[2 * q + 1] - bh(h));
            }
            uint32_t ad = row * 128 + (((uint32_t)(g * 16)) ^ ((row & 7) << 4));
            sts128(sXh + ad, H[0], H[1], H[2], H[3]);
            sts128(sXl + ad, L[0], L[1], L[2], L[3]);
        }
        __syncthreads();
        if (c < 7) {
            issueX(c + 1);
            issueA(c + 1, sb + ((c + 1) & 1 ? OFF_A1 : OFF_A0));
            CP_COMMIT();
        } else {
            issueV(0, sStage, sStage + 16384);   // stage free after conversion
            CP_COMMIT();
        }
        uint32_t bufAh = sb + ((c & 1) ? OFF_A1 : OFF_A0);
        uint32_t bufAl = bufAh + 8192;
        #pragma unroll
        for (int ks = 0; ks < 4; ks++) {
            uint32_t ic = (lcolb + ks * 32) ^ xw;
            uint32_t ah[4], al[4];
            ldsm4(ah, sXh + arowb + ic);
            ldsm4(al, sXl + arowb + ic);
            #pragma unroll
            for (int p = 0; p < 4; p++) {
                uint32_t ro = (lrow + p * 16) * 128;
                uint32_t bhr[4], blr[4];
                ldsm4(bhr, bufAh + ro + ic);
                ldsm4(blr, bufAl + ro + ic);
                mma16816(acc[2 * p],     ah, bhr[0], bhr[2]);
                mma16816(acc[2 * p],     ah, blr[0], blr[2]);
                mma16816(acc[2 * p],     al, bhr[0], bhr[2]);
                mma16816(acc[2 * p + 1], ah, bhr[1], bhr[3]);
                mma16816(acc[2 * p + 1], ah, blr[1], blr[3]);
                mma16816(acc[2 * p + 1], al, bhr[1], bhr[3]);
            }
        }
    }
    __syncthreads();                       // MMA(7) done: A + X regions free
    issueV(1, sb + OFF_A0, sb + OFF_A1); CP_COMMIT();
    issueV(2, sXh, sXl);                 CP_COMMIT();

    // ======= Y: register repack acc (C-frag) -> phase-2 A-frags (hi/lo) =====
    uint32_t yh[4][4], yl[4][4];
    #pragma unroll
    for (int kb = 0; kb < 4; kb++) {
        uint32_t h;
        h = cvt2(acc[2*kb][0],   acc[2*kb][1]);   yh[kb][0] = h;
        yl[kb][0] = cvt2(acc[2*kb][0] - bl(h),    acc[2*kb][1] - bh(h));
        h = cvt2(acc[2*kb][2],   acc[2*kb][3]);   yh[kb][1] = h;
        yl[kb][1] = cvt2(acc[2*kb][2] - bl(h),    acc[2*kb][3] - bh(h));
        h = cvt2(acc[2*kb+1][0], acc[2*kb+1][1]); yh[kb][2] = h;
        yl[kb][2] = cvt2(acc[2*kb+1][0] - bl(h),  acc[2*kb+1][1] - bh(h));
        h = cvt2(acc[2*kb+1][2], acc[2*kb+1][3]); yh[kb][3] = h;
        yl[kb][3] = cvt2(acc[2*kb+1][2] - bl(h),  acc[2*kb+1][3] - bh(h));
    }

    // ================= Phase 2: Z = Y V^T, out = X - Z  (4 n-chunks) ========
    const uint32_t vhOff[4] = {OFF_STAGE, OFF_A0, OFF_XH, OFF_STAGE};
    const uint32_t vlOff[4] = {OFF_STAGE + 16384, OFF_A1, OFF_XL, OFF_STAGE + 16384};
    #pragma unroll
    for (int j = 0; j < 4; j++) {
        if (j <= 1) { CP_WAIT(2); } else if (j == 2) { CP_WAIT(1); } else { CP_WAIT(0); }
        __syncthreads();
        uint32_t bufVh = sb + vhOff[j], bufVl = sb + vlOff[j];

        float z[16][4];
        #pragma unroll
        for (int i = 0; i < 16; i++)
            z[i][0] = z[i][1] = z[i][2] = z[i][3] = 0.f;

        #pragma unroll
        for (int ks = 0; ks < 4; ks++) {
            uint32_t ic = (lcolb + ks * 32) ^ xw;
            #pragma unroll
            for (int p = 0; p < 8; p++) {
                uint32_t ro = (lrow + p * 16) * 128;
                uint32_t bhr[4], blr[4];
                ldsm4(bhr, bufVh + ro + ic);
                ldsm4(blr, bufVl + ro + ic);
                mma16816(z[2 * p],     yh[ks], bhr[0], bhr[2]);
                mma16816(z[2 * p],     yh[ks], blr[0], blr[2]);
                mma16816(z[2 * p],     yl[ks], bhr[0], bhr[2]);
                mma16816(z[2 * p + 1], yh[ks], bhr[1], bhr[3]);
                mma16816(z[2 * p + 1], yh[ks], blr[1], blr[3]);
                mma16816(z[2 * p + 1], yl[ks], bhr[1], bhr[3]);
            }
        }
        if (j == 0) {   // all warps done reading V0 -> stage free for V3
            __syncthreads();
            issueV(3, sStage, sStage + 16384);
            CP_COMMIT();
        }

        // epilogue: out = x - z (fragment-mapped float2; x re-read hits L2)
        int r0 = m0 + mw + (lane >> 2);
        const float* x0p = x + (size_t)r0 * Dv;
        const float* x1p = x0p + 8 * Dv;
        float* o0 = out + (size_t)r0 * Dv;
        float* o1 = o0 + 8 * Dv;
        int cbase = (j << 7) + ((lane & 3) << 1);
        #pragma unroll
        for (int nt = 0; nt < 16; nt++) {
            int cc = cbase + nt * 8;
            float2 a0 = *(const float2*)(x0p + cc);
            float2 a1 = *(const float2*)(x1p + cc);
            float2 w0 = make_float2(a0.x - z[nt][0], a0.y - z[nt][1]);
            float2 w1 = make_float2(a1.x - z[nt][2], a1.y - z[nt][3]);
            *(float2*)(o0 + cc) = w0;
            *(float2*)(o1 + cc) = w1;
        }
    }

    if (outSldj != nullptr && tid < TM) {
        outSldj[m0 + tid] = sldj[m0 + tid];
    }
}

extern "C" void kernel_launch(void* const* d_in, const int* in_sizes, int n_in,
                              void* d_out, int out_size) {
    const float* x    = (const float*)d_in[0];   // (B, D)
    const float* sldj = (const float*)d_in[1];   // (B,)
    const float* P    = (const float*)d_in[2];   // (D, R)
    int BD = in_sizes[0];
    int Bn = in_sizes[1];
    (void)n_in;
    float* out = (float*)d_out;
    float* osl = (out_size >= BD + Bn) ? (out + BD) : nullptr;

    k_gram<<<64, 256>>>(P);
    cudaFuncSetAttribute(k_pack, cudaFuncAttributeMaxDynamicSharedMemorySize,
                         PR_FLOATS * 4);
    k_pack<<<12, 512, PR_FLOATS * 4>>>(P);

    cudaFuncSetAttribute(k_gemm, cudaFuncAttributeMaxDynamicSharedMemorySize, SMEM_BYTES);
    k_gemm<<<Bn / TM, NTHREADS, SMEM_BYTES>>>(x, out, sldj, osl);
}

// round 12
// speedup vs baseline: 1.5889x; 1.0665x over previous
#include <cuda_runtime.h>
#include <cuda_bf16.h>
#include <cstdint>

#define Dv 512
#define Rv 64
#define TM 128
#define NTHREADS 256

// ---------------------------------------------------------------------------
// Device scratch
// ---------------------------------------------------------------------------
__device__ float g_G0p[4 * 4096];  // Gram partials (4 d-quarters)
// Pre-packed bf16 hi/lo operand tiles, 128B rows, SW128-swizzled
__device__ __align__(16) __nv_bfloat16 g_Abh[8 * 64 * 64];   // chunk c: [r][kk]
__device__ __align__(16) __nv_bfloat16 g_Abl[8 * 64 * 64];
__device__ __align__(16) __nv_bfloat16 g_Vbh[4 * 128 * 64];  // n-chunk j: [n][r]
__device__ __align__(16) __nv_bfloat16 g_Vbl[4 * 128 * 64];

// ---------------------------------------------------------------------------
// Helpers
// ---------------------------------------------------------------------------
#define SWZ(o) ((o) ^ (((o) >> 3) & 0x70))

__device__ __forceinline__ uint32_t smem_to_u32(const void* p) {
    uint32_t a;
    asm("{ .reg .u64 t; cvta.to.shared.u64 t, %1; cvt.u32.u64 %0, t; }" : "=r"(a) : "l"(p));
    return a;
}
__device__ __forceinline__ void ldsm4(uint32_t* r, uint32_t addr) {
    asm volatile("ldmatrix.sync.aligned.m8n8.x4.shared.b16 {%0,%1,%2,%3}, [%4];"
                 : "=r"(r[0]), "=r"(r[1]), "=r"(r[2]), "=r"(r[3]) : "r"(addr));
}
__device__ __forceinline__ void mma16816(float* c, const uint32_t* a,
                                         uint32_t b0, uint32_t b1) {
    asm volatile("mma.sync.aligned.m16n8k16.row.col.f32.bf16.bf16.f32 "
                 "{%0,%1,%2,%3}, {%4,%5,%6,%7}, {%8,%9}, {%0,%1,%2,%3};"
                 : "+f"(c[0]), "+f"(c[1]), "+f"(c[2]), "+f"(c[3])
                 : "r"(a[0]), "r"(a[1]), "r"(a[2]), "r"(a[3]), "r"(b0), "r"(b1));
}
__device__ __forceinline__ float2 lds64(uint32_t a) {
    float2 v;
    asm volatile("ld.shared.v2.f32 {%0,%1}, [%2];" : "=f"(v.x), "=f"(v.y) : "r"(a));
    return v;
}
__device__ __forceinline__ void cpasync16(uint32_t dst, const void* src) {
    asm volatile("cp.async.cg.shared.global [%0], [%1], 16;"
                 :: "r"(dst), "l"(src) : "memory");
}
#define CP_COMMIT() asm volatile("cp.async.commit_group;" ::: "memory")
#define CP_WAIT(N)  asm volatile("cp.async.wait_group %0;" :: "n"(N) : "memory")

__device__ __forceinline__ uint32_t cvt2(float f0, float f1) {
    uint32_t r;
    asm("cvt.rn.bf16x2.f32 %0, %1, %2;" : "=r"(r) : "f"(f1), "f"(f0));
    return r;
}
__device__ __forceinline__ float bl(uint32_t h) { return __uint_as_float(h << 16); }
__device__ __forceinline__ float bh(uint32_t h) { return __uint_as_float(h & 0xFFFF0000u); }

// ---------------------------------------------------------------------------
// Precompute 1: Gram partials. 256 blocks (64 j x 4 d-quarters) x 256 thr.
// ---------------------------------------------------------------------------
__global__ __launch_bounds__(256) void k_gram(const float* __restrict__ P) {
    __shared__ float red[4][64];
    int bid = blockIdx.x;
    int j = bid & 63, q = bid >> 6;
    int k = threadIdx.x & 63, g = threadIdx.x >> 6;
    const float* p = P + (q * 128 + g * 32) * 64;
    float a[8] = {};
    #pragma unroll
    for (int d = 0; d < 32; d += 8) {
        #pragma unroll
        for (int e = 0; e < 8; e++)
            a[e] += __ldg(p + (d + e) * 64 + j) * __ldg(p + (d + e) * 64 + k);
    }
    red[g][k] = ((a[0] + a[1]) + (a[2] + a[3])) + ((a[4] + a[5]) + (a[6] + a[7]));
    __syncthreads();
    if (g == 0)
        g_G0p[q * 4096 + j * 64 + k] =
            (red[0][k] + red[1][k]) + (red[2][k] + red[3][k]);
}

// ---------------------------------------------------------------------------
// Precompute 2: 12 blocks x 512 thr (scan back-sub, validated R11).
// ---------------------------------------------------------------------------
#define PR_RV  0            // 64
#define PR_M   64           // 64*65
#define PR_W2  4224         // 64*65
#define PR_SP  8384         // 64*68
#define PR_PV  64           // 128*65 (V path overlaps M/W2)
#define PR_FLOATS 12736

__global__ __launch_bounds__(512) void k_pack(const float* __restrict__ P) {
    extern __shared__ float sm[];
    int bid = blockIdx.x, tid = threadIdx.x, w = tid >> 5, lane = tid & 31;

    if (tid < 64) {
        float s = g_G0p[tid * 65] + g_G0p[4096 + tid * 65]
                + g_G0p[8192 + tid * 65] + g_G0p[12288 + tid * 65];
        sm[PR_RV + tid] = rsqrtf(s);
    }
    __syncthreads();

    if (bid < 8) {
        int c = bid;
        for (int idx = tid; idx < 4096; idx += 512) {
            int i = idx >> 6, l = idx & 63;
            float gv = g_G0p[idx] + g_G0p[4096 + idx]
                     + g_G0p[8192 + idx] + g_G0p[12288 + idx];
            sm[PR_M + i * 65 + l] = 2.f * gv * sm[PR_RV + i] * sm[PR_RV + l];
        }
        for (int idx = tid; idx < 4096; idx += 512)
            sm[PR_SP + (idx >> 6) * 68 + (idx & 63)] = P[c * 4096 + idx];
        __syncthreads();

        // scan back-substitution: warp w solves cols {w, w+16, w+32, w+48}
        {
            float S0[4] = {0.f, 0.f, 0.f, 0.f};
            float S1[4] = {0.f, 0.f, 0.f, 0.f};
            float wv0[4] = {0.f, 0.f, 0.f, 0.f};
            float wv1[4] = {0.f, 0.f, 0.f, 0.f};
            for (int i = 63; i >= 0; --i) {
                float m0 = sm[PR_M + i * 65 + lane];
                float m1 = sm[PR_M + i * 65 + lane + 32];
                #pragma unroll
                for (int q = 0; q < 4; q++) {
                    int cq = w + 16 * q;
                    float sown = (i < 32) ? S0[q] : S1[q];
                    float s_i = __shfl_sync(0xFFFFFFFFu, sown, i & 31);
                    float wi = (i > cq) ? 0.f : ((i == cq) ? 1.f : -s_i);
                    if (lane == i)      wv0[q] = wi;
                    if (lane + 32 == i) wv1[q] = wi;
                    if (lane < i)       S0[q] += m0 * wi;
                    if (lane + 32 < i)  S1[q] += m1 * wi;
                }
            }
            #pragma unroll
            for (int q = 0; q < 4; q++) {
                int cq = w + 16 * q;
                sm[PR_W2 + lane * 65 + cq]        = 2.f * sm[PR_RV + lane] * wv0[q];
                sm[PR_W2 + (lane + 32) * 65 + cq] = 2.f * sm[PR_RV + lane + 32] * wv1[q];
            }
        }
        __syncthreads();

        int rr = tid & 63, kb = (tid >> 6) << 3;
        float pacc[8] = {};
        #pragma unroll 4
        for (int jj = 0; jj < 64; jj++) {
            float wv = sm[PR_W2 + jj * 65 + rr];
            #pragma unroll
            for (int e = 0; e < 8; e++)
                pacc[e] += sm[PR_SP + (kb + e) * 68 + jj] * wv;
        }
        #pragma unroll
        for (int e = 0; e < 8; e++) {
            float v = pacc[e];
            __nv_bfloat16 h = __float2bfloat16_rn(v);
            float lo = v - __bfloat162float(h);
            uint32_t off = c * 8192 + SWZ((uint32_t)(rr * 128 + (kb + e) * 2));
            *(__nv_bfloat16*)((char*)g_Abh + off) = h;
            *(__nv_bfloat16*)((char*)g_Abl + off) = __float2bfloat16_rn(lo);
        }
    } else {
        int jn = bid - 8;
        for (int idx = tid; idx < 8192; idx += 512)
            sm[PR_PV + (idx >> 6) * 65 + (idx & 63)] = P[jn * 8192 + idx];
        __syncthreads();
        for (int idx = tid; idx < 8192; idx += 512) {
            int n = idx >> 6, r = idx & 63;
            float v = sm[PR_PV + n * 65 + r] * sm[PR_RV + r];
            __nv_bfloat16 h = __float2bfloat16_rn(v);
            float lo = v - __bfloat162float(h);
            uint32_t off = jn * 16384 + SWZ((uint32_t)(n * 128 + r * 2));
            *(__nv_bfloat16*)((char*)g_Vbh + off) = h;
            *(__nv_bfloat16*)((char*)g_Vbl + off) = __float2bfloat16_rn(lo);
        }
    }
}

// ---------------------------------------------------------------------------
// Main kernel. X: warp-private fp32 stage blocks; A-frags built by LDS64+cvt
// (no Xh/Xl smem). smem (96KB, 2 CTA/SM):
//   [0,     32768)  stage: 8 warp blocks x 4KB     / phase2 V buf SB (j=1)
//   [32768, 65536)  FREE -> V0 (prefetched ph.1)   / then V3 (j=0,3 buf FB)
//   [65536, 98304)  A ping(16K)+pong(16K)          / phase2 V buf AB (j=2)
// ---------------------------------------------------------------------------
#define OFF_STAGE 0
#define OFF_FREE  32768
#define OFF_A0    65536
#define OFF_A1    81920
#define SMEM_BYTES 98304

__global__ __launch_bounds__(NTHREADS, 2) void k_gemm(const float* __restrict__ x,
                                                      float* __restrict__ out,
                                                      const float* __restrict__ sldj,
                                                      float* __restrict__ outSldj) {
    extern __shared__ char smem[];
    uint32_t sb = smem_to_u32(smem);

    int tid = threadIdx.x, wid = tid >> 5, lane = tid & 31;
    int m0 = blockIdx.x * TM;
    int mw = wid << 4;

    // B-side ldsm addressing (tiles with 128B rows, SW128)
    uint32_t lrow = lane & 15;
    uint32_t lcolb = (lane >> 4) << 4;
    uint32_t xwB = (lrow & 7) << 4;

    // A-side (warp-private stage): lane covers rows r, r+8; col pair base
    int r = lane >> 2;
    uint32_t rot = (uint32_t)(r & 7) << 5;
    uint32_t o3 = (uint32_t)(lane & 1) * 8;
    uint32_t sbStageW = sb + OFF_STAGE + wid * 4096;
    uint32_t rowbase = sbStageW + r * 256 + o3;
    int cpair = (lane >> 1) & 1;                   // (lane&3)>>1

    auto issueA = [&](int c, uint32_t buf) {
        const char* srch = (const char*)g_Abh + c * 8192;
        const char* srcl = (const char*)g_Abl + c * 8192;
        for (int idx = tid; idx < 512; idx += NTHREADS) {
            cpasync16(buf + idx * 16, srch + idx * 16);
            cpasync16(buf + 8192 + idx * 16, srcl + idx * 16);
        }
    };
    auto issueXown = [&](int c) {
        #pragma unroll
        for (int u = 0; u < 8; u++) {
            int unit = lane + u * 32;
            int lr = unit >> 4, i16 = unit & 15;
            uint32_t dst = sbStageW + lr * 256 +
                           (((uint32_t)(i16 * 16)) ^ ((uint32_t)(lr & 7) << 5));
            const char* src = (const char*)(x + (size_t)(m0 + mw + lr) * Dv
                                            + c * 64 + i16 * 4);
            cpasync16(dst, src);
        }
    };
    auto issueV = [&](int j, uint32_t buf) {       // hi at buf, lo at buf+16K
        const char* srch = (const char*)g_Vbh + j * 16384;
        const char* srcl = (const char*)g_Vbl + j * 16384;
        for (int idx = tid; idx < 1024; idx += NTHREADS) {
            cpasync16(buf + idx * 16, srch + idx * 16);
            cpasync16(buf + 16384 + idx * 16, srcl + idx * 16);
        }
    };

    float acc[8][4];
    #pragma unroll
    for (int i = 0; i < 8; i++)
        acc[i][0] = acc[i][1] = acc[i][2] = acc[i][3] = 0.f;

    // prologue: A0 + own X0
    issueA(0, sb + OFF_A0);
    issueXown(0);
    CP_COMMIT();

    // ================= Phase 1: Y = X A  (8 k-chunks of 64) =================
    for (int c = 0; c < 8; c++) {
        CP_WAIT(0);
        __syncthreads();                    // A(c) + X(c) visible everywhere
        if (c < 7) { issueA(c + 1, sb + (((c + 1) & 1) ? OFF_A1 : OFF_A0)); CP_COMMIT(); }

        uint32_t bufAh = sb + ((c & 1) ? OFF_A1 : OFF_A0);
        uint32_t bufAl = bufAh + 8192;
        #pragma unroll
        for (int ks = 0; ks < 4; ks++) {
            // A-frags directly from fp32 stage
            int b0 = 4 * ks + cpair;
            uint32_t u0 = ((uint32_t)(b0 * 16)) ^ rot;
            uint32_t u1 = ((uint32_t)((b0 + 2) * 16)) ^ rot;
            float2 fa = lds64(rowbase + u0);
            float2 fb = lds64(rowbase + 2048 + u0);
            float2 fc = lds64(rowbase + u1);
            float2 fd = lds64(rowbase + 2048 + u1);
            uint32_t ah[4], al[4];
            ah[0] = cvt2(fa.x, fa.y); al[0] = cvt2(fa.x - bl(ah[0]), fa.y - bh(ah[0]));
            ah[1] = cvt2(fb.x, fb.y); al[1] = cvt2(fb.x - bl(ah[1]), fb.y - bh(ah[1]));
            ah[2] = cvt2(fc.x, fc.y); al[2] = cvt2(fc.x - bl(ah[2]), fc.y - bh(ah[2]));
            ah[3] = cvt2(fd.x, fd.y); al[3] = cvt2(fd.x - bl(ah[3]), fd.y - bh(ah[3]));

            uint32_t ic = (lcolb + ks * 32) ^ xwB;
            #pragma unroll
            for (int p = 0; p < 4; p++) {
                uint32_t ro = (lrow + p * 16) * 128;
                uint32_t bhr[4], blr[4];
                ldsm4(bhr, bufAh + ro + ic);
                ldsm4(blr, bufAl + ro + ic);
                mma16816(acc[2 * p],     ah, bhr[0], bhr[2]);
                mma16816(acc[2 * p],     ah, blr[0], blr[2]);
                mma16816(acc[2 * p],     al, bhr[0], bhr[2]);
                mma16816(acc[2 * p + 1], ah, bhr[1], bhr[3]);
                mma16816(acc[2 * p + 1], ah, blr[1], blr[3]);
                mma16816(acc[2 * p + 1], al, bhr[1], bhr[3]);
            }
        }
        // per-warp X prefetch: own stage rows free after own LDS reads above
        if (c < 7) {
            issueXown(c + 1);
            if (c == 5) issueV(0, sb + OFF_FREE);   // V0 rides along, hidden
            CP_COMMIT();
        }
    }
    __syncthreads();                         // phase 1 fully done
    issueV(1, sb + OFF_STAGE); CP_COMMIT();  // SB
    issueV(2, sb + OFF_A0);    CP_COMMIT();  // AB (32K spanning ping+pong)

    // ======= Y: register repack acc (C-frag) -> phase-2 A-frags (hi/lo) =====
    uint32_t yh[4][4], yl[4][4];
    #pragma unroll
    for (int kb = 0; kb < 4; kb++) {
        uint32_t h;
        h = cvt2(acc[2*kb][0],   acc[2*kb][1]);   yh[kb][0] = h;
        yl[kb][0] = cvt2(acc[2*kb][0] - bl(h),    acc[2*kb][1] - bh(h));
        h = cvt2(acc[2*kb][2],   acc[2*kb][3]);   yh[kb][1] = h;
        yl[kb][1] = cvt2(acc[2*kb][2] - bl(h),    acc[2*kb][3] - bh(h));
        h = cvt2(acc[2*kb+1][0], acc[2*kb+1][1]); yh[kb][2] = h;
        yl[kb][2] = cvt2(acc[2*kb+1][0] - bl(h),  acc[2*kb+1][1] - bh(h));
        h = cvt2(acc[2*kb+1][2], acc[2*kb+1][3]); yh[kb][3] = h;
        yl[kb][3] = cvt2(acc[2*kb+1][2] - bl(h),  acc[2*kb+1][3] - bh(h));
    }

    // ================= Phase 2: Z = Y V^T, out = X - Z  (4 n-chunks) ========
    // buffers: j0 FB(V0, already resident), j1 SB(V1), j2 AB(V2), j3 FB(V3)
    const uint32_t vOff[4] = {OFF_FREE, OFF_STAGE, OFF_A0, OFF_FREE};
    #pragma unroll
    for (int j = 0; j < 4; j++) {
        if (j == 1)      { CP_WAIT(2); __syncthreads(); }
        else if (j == 2) { CP_WAIT(1); __syncthreads(); }
        else if (j == 3) { CP_WAIT(0); __syncthreads(); }
        uint32_t bufVh = sb + vOff[j], bufVl = bufVh + 16384;

        float z[16][4];
        #pragma unroll
        for (int i = 0; i < 16; i++)
            z[i][0] = z[i][1] = z[i][2] = z[i][3] = 0.f;

        #pragma unroll
        for (int ks = 0; ks < 4; ks++) {
            uint32_t ic = (lcolb + ks * 32) ^ xwB;
            #pragma unroll
            for (int p = 0; p < 8; p++) {
                uint32_t ro = (lrow + p * 16) * 128;
                uint32_t bhr[4], blr[4];
                ldsm4(bhr, bufVh + ro + ic);
                ldsm4(blr, bufVl + ro + ic);
                mma16816(z[2 * p],     yh[ks], bhr[0], bhr[2]);
                mma16816(z[2 * p],     yh[ks], blr[0], blr[2]);
                mma16816(z[2 * p],     yl[ks], bhr[0], bhr[2]);
                mma16816(z[2 * p + 1], yh[ks], bhr[1], bhr[3]);
                mma16816(z[2 * p + 1], yh[ks], blr[1], blr[3]);
                mma16816(z[2 * p + 1], yl[ks], bhr[1], bhr[3]);
            }
        }
        if (j == 0) {    // FB consumed by all warps -> host V3
            __syncthreads();
            issueV(3, sb + OFF_FREE);
            CP_COMMIT();
        }

        // epilogue: out = x - z (fragment-mapped float2; x re-read hits L2)
        int r0 = m0 + mw + (lane >> 2);
        const float* x0p = x + (size_t)r0 * Dv;
        const float* x1p = x0p + 8 * Dv;
        float* o0 = out + (size_t)r0 * Dv;
        float* o1 = o0 + 8 * Dv;
        int cbase = (j << 7) + ((lane & 3) << 1);
        #pragma unroll
        for (int nt = 0; nt < 16; nt++) {
            int cc = cbase + nt * 8;
            float2 a0 = *(const float2*)(x0p + cc);
            float2 a1 = *(const float2*)(x1p + cc);
            float2 w0 = make_float2(a0.x - z[nt][0], a0.y - z[nt][1]);
            float2 w1 = make_float2(a1.x - z[nt][2], a1.y - z[nt][3]);
            *(float2*)(o0 + cc) = w0;
            *(float2*)(o1 + cc) = w1;
        }
    }

    if (outSldj != nullptr && tid < TM) {
        outSldj[m0 + tid] = sldj[m0 + tid];
    }
}

extern "C" void kernel_launch(void* const* d_in, const int* in_sizes, int n_in,
                              void* d_out, int out_size) {
    const float* x    = (const float*)d_in[0];   // (B, D)
    const float* sldj = (const float*)d_in[1];   // (B,)
    const float* P    = (const float*)d_in[2];   // (D, R)
    int BD = in_sizes[0];
    int Bn = in_sizes[1];
    (void)n_in;
    float* out = (float*)d_out;
    float* osl = (out_size >= BD + Bn) ? (out + BD) : nullptr;

    k_gram<<<256, 256>>>(P);
    cudaFuncSetAttribute(k_pack, cudaFuncAttributeMaxDynamicSharedMemorySize,
                         PR_FLOATS * 4);
    k_pack<<<12, 512, PR_FLOATS * 4>>>(P);

    cudaFuncSetAttribute(k_gemm, cudaFuncAttributeMaxDynamicSharedMemorySize, SMEM_BYTES);
    k_gemm<<<Bn / TM, NTHREADS, SMEM_BYTES>>>(x, out, sldj, osl);
}